// round 2
// baseline (speedup 1.0000x reference)
#include <cuda_runtime.h>
#include <math.h>

#define S_LEN   2048
#define BATCH   2
#define HID     4096
#define NHEADS  32
#define HD      128
#define M_ROWS  (BATCH * S_LEN)     /* 4096 */
#define QKV_N   (3 * HID)           /* 12288 */

#define NEG_BIG (-1e30f)

// Scratch (allocation-free rule: __device__ globals)
__device__ float g_qkv[(size_t)M_ROWS * QKV_N];   // [B*S, 3H]
__device__ float g_ctx[(size_t)M_ROWS * HID];     // [B*S, H]

// ---------------------------------------------------------------------------
// SGEMM + bias: C[M,N] = A[M,K] @ B[K,N] + bias[N]   (all row-major fp32)
// 128x128 block tile, 8x8 per thread, K-step 8, 256 threads.
// M,N multiples of 128; K multiple of 8 (true for all uses here).
// ---------------------------------------------------------------------------
__global__ __launch_bounds__(256, 2)
void sgemm_bias(const float* __restrict__ A, const float* __restrict__ Bm,
                const float* __restrict__ bias, float* __restrict__ C,
                int M, int N, int K)
{
    __shared__ float As[8][132];   // [k][row], padded: conflict-free transpose store
    __shared__ float Bs[8][128];   // [k][col]

    const int tid = threadIdx.x;
    const int tx = tid & 15;
    const int ty = tid >> 4;
    const int bx = blockIdx.x;
    const int by = blockIdx.y;

    const int arow = tid >> 1;            // 0..127
    const int acol = (tid & 1) * 4;       // 0 or 4
    const int brow = tid >> 5;            // 0..7
    const int bcol = (tid & 31) * 4;      // 0..124

    const float* Aptr = A + (size_t)(by * 128 + arow) * K + acol;
    const float* Bptr = Bm + (size_t)brow * N + (size_t)bx * 128 + bcol;

    float acc[8][8];
#pragma unroll
    for (int i = 0; i < 8; i++)
#pragma unroll
        for (int j = 0; j < 8; j++) acc[i][j] = 0.f;

    for (int k0 = 0; k0 < K; k0 += 8) {
        const float4 av = *(const float4*)(Aptr + k0);
        const float4 bv = *(const float4*)(Bptr + (size_t)k0 * N);
        __syncthreads();                    // protect previous iter's smem reads
        As[acol + 0][arow] = av.x;
        As[acol + 1][arow] = av.y;
        As[acol + 2][arow] = av.z;
        As[acol + 3][arow] = av.w;
        *(float4*)&Bs[brow][bcol] = bv;
        __syncthreads();
#pragma unroll
        for (int kk = 0; kk < 8; kk++) {
            float a[8], b[8];
            *(float4*)&a[0] = *(const float4*)&As[kk][ty * 8];
            *(float4*)&a[4] = *(const float4*)&As[kk][ty * 8 + 4];
            *(float4*)&b[0] = *(const float4*)&Bs[kk][tx * 8];
            *(float4*)&b[4] = *(const float4*)&Bs[kk][tx * 8 + 4];
#pragma unroll
            for (int i = 0; i < 8; i++)
#pragma unroll
                for (int j = 0; j < 8; j++)
                    acc[i][j] += a[i] * b[j];
        }
    }

    const int crow = by * 128 + ty * 8;
    const int ccol = bx * 128 + tx * 8;
#pragma unroll
    for (int i = 0; i < 8; i++) {
        float4 o0, o1;
        o0.x = acc[i][0] + bias[ccol + 0];
        o0.y = acc[i][1] + bias[ccol + 1];
        o0.z = acc[i][2] + bias[ccol + 2];
        o0.w = acc[i][3] + bias[ccol + 3];
        o1.x = acc[i][4] + bias[ccol + 4];
        o1.y = acc[i][5] + bias[ccol + 5];
        o1.z = acc[i][6] + bias[ccol + 6];
        o1.w = acc[i][7] + bias[ccol + 7];
        float* cp = C + (size_t)(crow + i) * N + ccol;
        *(float4*)(cp)     = o0;
        *(float4*)(cp + 4) = o1;
    }
}

// ---------------------------------------------------------------------------
// Flash attention fp32: per (b,h), Br=64 q rows per block, Bc=64 key tiles,
// online softmax. qkv layout: [B, S, 3, NHEADS, HD] flattened.
// grid = (S/64, B*NHEADS), block = 256.
// ---------------------------------------------------------------------------
#define FLASH_SMEM_FLOATS (3 * 64 * 132 + 64 * 65 + 3 * 64)
#define FLASH_SMEM_BYTES  (FLASH_SMEM_FLOATS * 4)

__global__ __launch_bounds__(256, 1)
void flash_attn(const float* __restrict__ qkv, float* __restrict__ ctx)
{
    extern __shared__ float sm[];
    float* Qs   = sm;                   // [64][132]
    float* Ks   = Qs + 64 * 132;        // [64][132]
    float* Vs   = Ks + 64 * 132;        // [64][132]
    float* Ss   = Vs + 64 * 132;        // [64][65]
    float* mrow = Ss + 64 * 65;         // [64]
    float* lrow = mrow + 64;            // [64]
    float* arow = lrow + 64;            // [64]

    const int tid = threadIdx.x;
    const int bh  = blockIdx.y;
    const int b   = bh >> 5;
    const int h   = bh & 31;
    const int qb  = blockIdx.x;
    const float scale = 0.088388347648318447f;   // 1/sqrt(128)

    const float* base = qkv + (size_t)b * S_LEN * QKV_N + (size_t)h * HD;
    const float* qg = base + (size_t)(qb * 64) * QKV_N;   // q: offset 0
    const float* kg = base + HID;                         // k: +H
    const float* vg = base + 2 * HID;                     // v: +2H

    // Load Q tile [64][128]
    for (int i = tid; i < 64 * 32; i += 256) {
        const int r = i >> 5;
        const int c = (i & 31) << 2;
        *(float4*)&Qs[r * 132 + c] = *(const float4*)(qg + (size_t)r * QKV_N + c);
    }
    if (tid < 64) { mrow[tid] = NEG_BIG; lrow[tid] = 0.f; }

    float acc[32];
#pragma unroll
    for (int i = 0; i < 32; i++) acc[i] = 0.f;

    const int sy = tid >> 4, sx = tid & 15;          // score: 4 rows x 4 cols
    const int pr = tid >> 2, pc = (tid & 3) * 32;    // PV: 1 row x 32 cols

    __syncthreads();

    for (int j = 0; j < S_LEN / 64; ++j) {
        // Load K,V tiles [64][128]
        for (int i = tid; i < 64 * 32; i += 256) {
            const int r = i >> 5;
            const int c = (i & 31) << 2;
            const size_t go = (size_t)(j * 64 + r) * QKV_N + c;
            *(float4*)&Ks[r * 132 + c] = *(const float4*)(kg + go);
            *(float4*)&Vs[r * 132 + c] = *(const float4*)(vg + go);
        }
        __syncthreads();

        // Scores: s[r][c] = q[r] . k[c], 4x4 per thread
        float s[4][4];
#pragma unroll
        for (int i = 0; i < 4; i++)
#pragma unroll
            for (int c = 0; c < 4; c++) s[i][c] = 0.f;
#pragma unroll 4
        for (int d = 0; d < HD; d += 4) {
            float4 qv[4], kv[4];
#pragma unroll
            for (int i = 0; i < 4; i++) qv[i] = *(const float4*)&Qs[(sy * 4 + i) * 132 + d];
#pragma unroll
            for (int c = 0; c < 4; c++) kv[c] = *(const float4*)&Ks[(sx * 4 + c) * 132 + d];
#pragma unroll
            for (int i = 0; i < 4; i++)
#pragma unroll
                for (int c = 0; c < 4; c++)
                    s[i][c] += qv[i].x * kv[c].x + qv[i].y * kv[c].y
                             + qv[i].z * kv[c].z + qv[i].w * kv[c].w;
        }
#pragma unroll
        for (int i = 0; i < 4; i++)
#pragma unroll
            for (int c = 0; c < 4; c++)
                Ss[(sy * 4 + i) * 65 + sx * 4 + c] = s[i][c] * scale;
        __syncthreads();

        // Online softmax row update (one thread per row)
        if (tid < 64) {
            const int r = tid;
            const float mold = mrow[r];
            float mt = mold;
#pragma unroll 8
            for (int c = 0; c < 64; c++) mt = fmaxf(mt, Ss[r * 65 + c]);
            const float alpha = __expf(mold - mt);
            float lt = 0.f;
#pragma unroll 8
            for (int c = 0; c < 64; c++) {
                const float p = __expf(Ss[r * 65 + c] - mt);
                Ss[r * 65 + c] = p;
                lt += p;
            }
            lrow[r] = lrow[r] * alpha + lt;
            mrow[r] = mt;
            arow[r] = alpha;
        }
        __syncthreads();

        // acc = acc*alpha + P @ V
        {
            const float alpha = arow[pr];
#pragma unroll
            for (int i = 0; i < 32; i++) acc[i] *= alpha;
#pragma unroll 4
            for (int c = 0; c < 64; c++) {
                const float p = Ss[pr * 65 + c];
                const float* vr = &Vs[c * 132 + pc];
#pragma unroll
                for (int i = 0; i < 32; i += 4) {
                    const float4 vv = *(const float4*)(vr + i);
                    acc[i + 0] += p * vv.x;
                    acc[i + 1] += p * vv.y;
                    acc[i + 2] += p * vv.z;
                    acc[i + 3] += p * vv.w;
                }
            }
        }
        __syncthreads();
    }

    // Epilogue: ctx[b, s, h*HD + d] = acc / l
    const float invl = 1.f / lrow[pr];
    float* og = ctx + (size_t)(b * S_LEN + qb * 64 + pr) * HID + h * HD + pc;
#pragma unroll
    for (int i = 0; i < 32; i += 4) {
        float4 o;
        o.x = acc[i + 0] * invl;
        o.y = acc[i + 1] * invl;
        o.z = acc[i + 2] * invl;
        o.w = acc[i + 3] * invl;
        *(float4*)(og + i) = o;
    }
}

// ---------------------------------------------------------------------------
extern "C" void kernel_launch(void* const* d_in, const int* in_sizes, int n_in,
                              void* d_out, int out_size)
{
    (void)in_sizes; (void)n_in; (void)out_size;
    const float* x    = (const float*)d_in[0];   // [B,S,H]
    const float* qkvw = (const float*)d_in[1];   // [H, 3H]
    const float* qkvb = (const float*)d_in[2];   // [3H]
    const float* ow   = (const float*)d_in[3];   // [H, H]
    const float* ob   = (const float*)d_in[4];   // [H]
    float* out = (float*)d_out;                  // [B,S,H]

    float* qkv = nullptr;
    float* ctx = nullptr;
    cudaGetSymbolAddress((void**)&qkv, g_qkv);
    cudaGetSymbolAddress((void**)&ctx, g_ctx);

    cudaFuncSetAttribute(flash_attn, cudaFuncAttributeMaxDynamicSharedMemorySize,
                         FLASH_SMEM_BYTES);

    // 1) QKV = x @ W_qkv + b_qkv
    sgemm_bias<<<dim3(QKV_N / 128, M_ROWS / 128), 256>>>(
        x, qkvw, qkvb, qkv, M_ROWS, QKV_N, HID);

    // 2) Flash attention -> ctx
    flash_attn<<<dim3(S_LEN / 64, BATCH * NHEADS), 256, FLASH_SMEM_BYTES>>>(qkv, ctx);

    // 3) out = ctx @ W_o + b_o
    sgemm_bias<<<dim3(HID / 128, M_ROWS / 128), 256>>>(
        ctx, ow, ob, out, M_ROWS, HID, HID);
}

// round 6
// speedup vs baseline: 1.2878x; 1.2878x over previous
#include <cuda_runtime.h>
#include <cuda_bf16.h>
#include <math.h>
#include <stdint.h>

#define S_LEN   2048
#define BATCH   2
#define HID     4096
#define NHEADS  32
#define HD      128
#define M_ROWS  (BATCH * S_LEN)     /* 4096 */
#define QKV_N   (3 * HID)           /* 12288 */
#define KEFF    (3 * HID)           /* 12288 = tripled K for error-split GEMM */
#define NEG_BIG (-1e30f)

// ---------------------------------------------------------------------------
// Scratch (allocation-free rule: __device__ globals)
// ---------------------------------------------------------------------------
__device__ float g_qkv[(size_t)M_ROWS * QKV_N];            // [B*S, 3H] fp32
__device__ float g_ctx[(size_t)M_ROWS * HID];              // [B*S, H]  fp32
__device__ __align__(16) __nv_bfloat16 g_xcat [(size_t)M_ROWS * KEFF];   // [M, 3K] = [hi|lo|hi]
__device__ __align__(16) __nv_bfloat16 g_ccat [(size_t)M_ROWS * KEFF];   // ctx split
__device__ __align__(16) __nv_bfloat16 g_wqcat[(size_t)QKV_N * KEFF];    // W_qkv^T: [N,3K]=[hi|hi|lo]
__device__ __align__(16) __nv_bfloat16 g_wocat[(size_t)HID   * KEFF];    // W_o^T

// ---------------------------------------------------------------------------
// helpers
// ---------------------------------------------------------------------------
__device__ __forceinline__ uint32_t su32(const void* p) {
    uint32_t a;
    asm("{ .reg .u64 t; cvta.to.shared.u64 t, %1; cvt.u32.u64 %0, t; }" : "=r"(a) : "l"(p));
    return a;
}
__device__ __forceinline__ void cpasync16(uint32_t saddr, const void* gaddr) {
    asm volatile("cp.async.cg.shared.global [%0], [%1], 16;" :: "r"(saddr), "l"(gaddr));
}
__device__ __forceinline__ void ldm_x4(uint32_t* r, uint32_t addr) {
    asm volatile("ldmatrix.sync.aligned.m8n8.x4.shared.b16 {%0,%1,%2,%3}, [%4];"
                 : "=r"(r[0]), "=r"(r[1]), "=r"(r[2]), "=r"(r[3]) : "r"(addr));
}
__device__ __forceinline__ void mma16816(float* c, const uint32_t* a, uint32_t b0, uint32_t b1) {
    asm volatile(
        "mma.sync.aligned.m16n8k16.row.col.f32.bf16.bf16.f32 "
        "{%0,%1,%2,%3}, {%4,%5,%6,%7}, {%8,%9}, {%0,%1,%2,%3};"
        : "+f"(c[0]), "+f"(c[1]), "+f"(c[2]), "+f"(c[3])
        : "r"(a[0]), "r"(a[1]), "r"(a[2]), "r"(a[3]), "r"(b0), "r"(b1));
}

// ---------------------------------------------------------------------------
// Pack activations: fp32 [M, K] -> bf16 [M, 3K] as [hi | lo | hi]
// ---------------------------------------------------------------------------
__global__ void pack_a(const float* __restrict__ in, __nv_bfloat16* __restrict__ out, int Mr)
{
    const int idx = blockIdx.x * blockDim.x + threadIdx.x;       // over M*K/2
    if (idx >= Mr * (HID / 2)) return;
    const int row = idx / (HID / 2);
    const int k   = (idx % (HID / 2)) * 2;
    const float2 f = *(const float2*)(in + (size_t)row * HID + k);
    const __nv_bfloat16 hx = __float2bfloat16(f.x);
    const __nv_bfloat16 hy = __float2bfloat16(f.y);
    const __nv_bfloat16 lx = __float2bfloat16(f.x - __bfloat162float(hx));
    const __nv_bfloat16 ly = __float2bfloat16(f.y - __bfloat162float(hy));
    const __nv_bfloat162 hi2 = __halves2bfloat162(hx, hy);
    const __nv_bfloat162 lo2 = __halves2bfloat162(lx, ly);
    __nv_bfloat16* base = out + (size_t)row * KEFF;
    *(__nv_bfloat162*)(base + k)            = hi2;
    *(__nv_bfloat162*)(base + HID + k)      = lo2;
    *(__nv_bfloat162*)(base + 2 * HID + k)  = hi2;
}

// ---------------------------------------------------------------------------
// Pack weights: fp32 [K, N] -> bf16 transposed [N, 3K] as [hi | hi | lo]
// ---------------------------------------------------------------------------
__global__ void pack_w(const float* __restrict__ in, __nv_bfloat16* __restrict__ outT, int N)
{
    __shared__ float t[32][33];
    const int nb = blockIdx.x * 32, kb = blockIdx.y * 32;
    const int tx = threadIdx.x, ty = threadIdx.y;
#pragma unroll
    for (int i = 0; i < 32; i += 8)
        t[ty + i][tx] = in[(size_t)(kb + ty + i) * N + nb + tx];
    __syncthreads();
#pragma unroll
    for (int i = 0; i < 32; i += 8) {
        const float f = t[tx][ty + i];                 // = in[kb+tx][nb+ty+i]
        const __nv_bfloat16 h = __float2bfloat16(f);
        const __nv_bfloat16 l = __float2bfloat16(f - __bfloat162float(h));
        const int n = nb + ty + i, k = kb + tx;
        __nv_bfloat16* base = outT + (size_t)n * KEFF;
        base[k]           = h;
        base[HID + k]     = h;
        base[2 * HID + k] = l;
    }
}

// ---------------------------------------------------------------------------
// bf16 mma.sync GEMM: C[M,Nd] = A'[M,Keff] @ B'[Nd,Keff]^T + bias
// 128x128 CTA tile, BK=32, 4-stage cp.async, 8 warps (4M x 2N), warp 32x64.
// smem rows padded to 80B (40 bf16) -> conflict-free ldmatrix.
// ---------------------------------------------------------------------------
#define GSTG        4
#define TILE_BYTES  10240u                /* 128 rows x 80B */
#define SLOT_BYTES  (2u * TILE_BYTES)     /* A + B */
#define GEMM_DSMEM  (GSTG * SLOT_BYTES)   /* 81920 */

__global__ __launch_bounds__(256, 2)
void gemm_bf16s(const __nv_bfloat16* __restrict__ A, const __nv_bfloat16* __restrict__ B,
                const float* __restrict__ bias, float* __restrict__ C, int Nd)
{
    extern __shared__ char smraw[];
    const uint32_t sbase = su32(smraw);

    const int tid  = threadIdx.x;
    const int lane = tid & 31, wid = tid >> 5;
    const int wm = (wid & 3) * 32, wn = (wid >> 2) * 64;
    const int m0 = blockIdx.y * 128, n0 = blockIdx.x * 128;
    const int nk = KEFF / 32;

    const __nv_bfloat16* Ag = A + (size_t)m0 * KEFF;
    const __nv_bfloat16* Bg = B + (size_t)n0 * KEFF;

    // cp.async mapping: thread -> (row, 16B chunk); covers rows 0-63, +64 on 2nd
    const int lrow = tid >> 2;                       // 0..63
    const int lcol = (tid & 3) * 8;                  // elem offset 0,8,16,24
    const uint32_t srowb = (uint32_t)lrow * 80u + (uint32_t)(tid & 3) * 16u;

    // ldmatrix bases
    const uint32_t aBase = (uint32_t)(wm + (lane & 15)) * 80u + (uint32_t)(lane >> 4) * 16u;
    const uint32_t bBase = (uint32_t)(wn + (lane & 15)) * 80u + (uint32_t)(lane >> 4) * 16u;

    float c[2][8][4];
#pragma unroll
    for (int i = 0; i < 2; i++)
#pragma unroll
        for (int j = 0; j < 8; j++)
#pragma unroll
            for (int q = 0; q < 4; q++) c[i][j][q] = 0.f;

#define G_ISSUE(KT, SLOT) do {                                                     \
        if ((KT) < nk) {                                                           \
            const uint32_t sa = sbase + (uint32_t)(SLOT) * SLOT_BYTES;             \
            const uint32_t sb = sa + TILE_BYTES;                                   \
            const __nv_bfloat16* ga = Ag + (size_t)lrow * KEFF + (KT) * 32 + lcol; \
            const __nv_bfloat16* gb = Bg + (size_t)lrow * KEFF + (KT) * 32 + lcol; \
            cpasync16(sa + srowb,               ga);                               \
            cpasync16(sa + srowb + 64u * 80u,   ga + (size_t)64 * KEFF);           \
            cpasync16(sb + srowb,               gb);                               \
            cpasync16(sb + srowb + 64u * 80u,   gb + (size_t)64 * KEFF);           \
        }                                                                          \
        asm volatile("cp.async.commit_group;" ::: "memory");                       \
    } while (0)

    G_ISSUE(0, 0);
    G_ISSUE(1, 1);
    G_ISSUE(2, 2);

#pragma unroll 1
    for (int kt = 0; kt < nk; kt++) {
        asm volatile("cp.async.wait_group 2;" ::: "memory");
        __syncthreads();
        G_ISSUE(kt + 3, (kt + 3) & 3);

        const uint32_t sa = sbase + (uint32_t)(kt & 3) * SLOT_BYTES;
        const uint32_t sb = sa + TILE_BYTES;
#pragma unroll
        for (int kk = 0; kk < 2; kk++) {
            uint32_t A0[4], A1[4];
            ldm_x4(A0, sa + aBase + kk * 32u);
            ldm_x4(A1, sa + aBase + 1280u + kk * 32u);   // +16 rows
#pragma unroll
            for (int p = 0; p < 4; p++) {
                uint32_t Bq[4];
                ldm_x4(Bq, sb + bBase + (uint32_t)p * 1280u + kk * 32u);
                mma16816(c[0][2 * p],     A0, Bq[0], Bq[2]);
                mma16816(c[0][2 * p + 1], A0, Bq[1], Bq[3]);
                mma16816(c[1][2 * p],     A1, Bq[0], Bq[2]);
                mma16816(c[1][2 * p + 1], A1, Bq[1], Bq[3]);
            }
        }
    }
#undef G_ISSUE

    // epilogue: add bias, store fp32
    const int gg = lane >> 2, tt = (lane & 3) * 2;
#pragma unroll
    for (int nt = 0; nt < 8; nt++) {
        const int col = n0 + wn + nt * 8 + tt;
        const float2 bb = *(const float2*)(bias + col);
#pragma unroll
        for (int mt = 0; mt < 2; mt++) {
            const int row = m0 + wm + mt * 16 + gg;
            float2 v0, v1;
            v0.x = c[mt][nt][0] + bb.x;  v0.y = c[mt][nt][1] + bb.y;
            v1.x = c[mt][nt][2] + bb.x;  v1.y = c[mt][nt][3] + bb.y;
            *(float2*)(C + (size_t)row * Nd + col)       = v0;
            *(float2*)(C + (size_t)(row + 8) * Nd + col) = v1;
        }
    }
}

// ---------------------------------------------------------------------------
// Flash attention fp32 (known-good from R1)
// ---------------------------------------------------------------------------
#define FLASH_SMEM_FLOATS (3 * 64 * 132 + 64 * 65 + 3 * 64)
#define FLASH_SMEM_BYTES  (FLASH_SMEM_FLOATS * 4)

__global__ __launch_bounds__(256, 1)
void flash_attn(const float* __restrict__ qkv, float* __restrict__ ctx)
{
    extern __shared__ float sm[];
    float* Qs   = sm;
    float* Ks   = Qs + 64 * 132;
    float* Vs   = Ks + 64 * 132;
    float* Ss   = Vs + 64 * 132;
    float* mrow = Ss + 64 * 65;
    float* lrow = mrow + 64;
    float* arow = lrow + 64;

    const int tid = threadIdx.x;
    const int bh  = blockIdx.y;
    const int b   = bh >> 5;
    const int h   = bh & 31;
    const int qb  = blockIdx.x;
    const float scale = 0.088388347648318447f;

    const float* base = qkv + (size_t)b * S_LEN * QKV_N + (size_t)h * HD;
    const float* qg = base + (size_t)(qb * 64) * QKV_N;
    const float* kg = base + HID;
    const float* vg = base + 2 * HID;

    for (int i = tid; i < 64 * 32; i += 256) {
        const int r = i >> 5;
        const int c = (i & 31) << 2;
        *(float4*)&Qs[r * 132 + c] = *(const float4*)(qg + (size_t)r * QKV_N + c);
    }
    if (tid < 64) { mrow[tid] = NEG_BIG; lrow[tid] = 0.f; }

    float acc[32];
#pragma unroll
    for (int i = 0; i < 32; i++) acc[i] = 0.f;

    const int sy = tid >> 4, sx = tid & 15;
    const int pr = tid >> 2, pc = (tid & 3) * 32;

    __syncthreads();

    for (int j = 0; j < S_LEN / 64; ++j) {
        for (int i = tid; i < 64 * 32; i += 256) {
            const int r = i >> 5;
            const int c = (i & 31) << 2;
            const size_t go = (size_t)(j * 64 + r) * QKV_N + c;
            *(float4*)&Ks[r * 132 + c] = *(const float4*)(kg + go);
            *(float4*)&Vs[r * 132 + c] = *(const float4*)(vg + go);
        }
        __syncthreads();

        float s[4][4];
#pragma unroll
        for (int i = 0; i < 4; i++)
#pragma unroll
            for (int c = 0; c < 4; c++) s[i][c] = 0.f;
#pragma unroll 4
        for (int d = 0; d < HD; d += 4) {
            float4 qv[4], kv[4];
#pragma unroll
            for (int i = 0; i < 4; i++) qv[i] = *(const float4*)&Qs[(sy * 4 + i) * 132 + d];
#pragma unroll
            for (int c = 0; c < 4; c++) kv[c] = *(const float4*)&Ks[(sx * 4 + c) * 132 + d];
#pragma unroll
            for (int i = 0; i < 4; i++)
#pragma unroll
                for (int c = 0; c < 4; c++)
                    s[i][c] += qv[i].x * kv[c].x + qv[i].y * kv[c].y
                             + qv[i].z * kv[c].z + qv[i].w * kv[c].w;
        }
#pragma unroll
        for (int i = 0; i < 4; i++)
#pragma unroll
            for (int c = 0; c < 4; c++)
                Ss[(sy * 4 + i) * 65 + sx * 4 + c] = s[i][c] * scale;
        __syncthreads();

        if (tid < 64) {
            const int r = tid;
            const float mold = mrow[r];
            float mt = mold;
#pragma unroll 8
            for (int c = 0; c < 64; c++) mt = fmaxf(mt, Ss[r * 65 + c]);
            const float alpha = __expf(mold - mt);
            float lt = 0.f;
#pragma unroll 8
            for (int c = 0; c < 64; c++) {
                const float p = __expf(Ss[r * 65 + c] - mt);
                Ss[r * 65 + c] = p;
                lt += p;
            }
            lrow[r] = lrow[r] * alpha + lt;
            mrow[r] = mt;
            arow[r] = alpha;
        }
        __syncthreads();

        {
            const float alpha = arow[pr];
#pragma unroll
            for (int i = 0; i < 32; i++) acc[i] *= alpha;
#pragma unroll 4
            for (int c = 0; c < 64; c++) {
                const float p = Ss[pr * 65 + c];
                const float* vr = &Vs[c * 132 + pc];
#pragma unroll
                for (int i = 0; i < 32; i += 4) {
                    const float4 vv = *(const float4*)(vr + i);
                    acc[i + 0] += p * vv.x;
                    acc[i + 1] += p * vv.y;
                    acc[i + 2] += p * vv.z;
                    acc[i + 3] += p * vv.w;
                }
            }
        }
        __syncthreads();
    }

    const float invl = 1.f / lrow[pr];
    float* og = ctx + (size_t)(b * S_LEN + qb * 64 + pr) * HID + h * HD + pc;
#pragma unroll
    for (int i = 0; i < 32; i += 4) {
        float4 o;
        o.x = acc[i + 0] * invl;
        o.y = acc[i + 1] * invl;
        o.z = acc[i + 2] * invl;
        o.w = acc[i + 3] * invl;
        *(float4*)(og + i) = o;
    }
}

// ---------------------------------------------------------------------------
// Host side
// ---------------------------------------------------------------------------
extern "C" void kernel_launch(void* const* d_in, const int* in_sizes, int n_in,
                              void* d_out, int out_size)
{
    (void)in_sizes; (void)n_in; (void)out_size;
    const float* x    = (const float*)d_in[0];
    const float* qkvw = (const float*)d_in[1];
    const float* qkvb = (const float*)d_in[2];
    const float* ow   = (const float*)d_in[3];
    const float* ob   = (const float*)d_in[4];
    float* out = (float*)d_out;

    float *qkv, *ctx;
    __nv_bfloat16 *xcat, *ccat, *wqcat, *wocat;
    cudaGetSymbolAddress((void**)&qkv,   g_qkv);
    cudaGetSymbolAddress((void**)&ctx,   g_ctx);
    cudaGetSymbolAddress((void**)&xcat,  g_xcat);
    cudaGetSymbolAddress((void**)&ccat,  g_ccat);
    cudaGetSymbolAddress((void**)&wqcat, g_wqcat);
    cudaGetSymbolAddress((void**)&wocat, g_wocat);

    cudaFuncSetAttribute(gemm_bf16s, cudaFuncAttributeMaxDynamicSharedMemorySize, GEMM_DSMEM);
    cudaFuncSetAttribute(flash_attn, cudaFuncAttributeMaxDynamicSharedMemorySize, FLASH_SMEM_BYTES);

    const int napack = M_ROWS * (HID / 2);

    // 1) pack x and W_qkv
    pack_a<<<(napack + 255) / 256, 256>>>(x, xcat, M_ROWS);
    pack_w<<<dim3(QKV_N / 32, HID / 32), dim3(32, 8)>>>(qkvw, wqcat, QKV_N);

    // 2) QKV = x @ W_qkv + b   (bf16 split mma.sync)
    gemm_bf16s<<<dim3(QKV_N / 128, M_ROWS / 128), 256, GEMM_DSMEM>>>(
        xcat, wqcat, qkvb, qkv, QKV_N);

    // 3) attention
    flash_attn<<<dim3(S_LEN / 64, BATCH * NHEADS), 256, FLASH_SMEM_BYTES>>>(qkv, ctx);

    // 4) pack ctx and W_o
    pack_a<<<(napack + 255) / 256, 256>>>(ctx, ccat, M_ROWS);
    pack_w<<<dim3(HID / 32, HID / 32), dim3(32, 8)>>>(ow, wocat, HID);

    // 5) out = ctx @ W_o + b
    gemm_bf16s<<<dim3(HID / 128, M_ROWS / 128), 256, GEMM_DSMEM>>>(
        ccat, wocat, ob, out, HID);
}

// round 7
// speedup vs baseline: 3.1895x; 2.4767x over previous
#include <cuda_runtime.h>
#include <cuda_fp16.h>
#include <math.h>
#include <stdint.h>

#define S_LEN   2048
#define BATCH   2
#define HID     4096
#define NHEADS  32
#define HD      128
#define M_ROWS  (BATCH * S_LEN)     /* 4096 */
#define QKV_N   (3 * HID)           /* 12288 */
#define KEFF    (2 * HID)           /* 8192 = doubled K for fp16 2-term split */
#define NEG_BIG (-1e30f)

// ---------------------------------------------------------------------------
// Scratch (allocation-free rule: __device__ globals)
// ---------------------------------------------------------------------------
__device__ float g_qkv[(size_t)M_ROWS * QKV_N];            // [B*S, 3H] fp32
__device__ float g_ctx[(size_t)M_ROWS * HID];              // [B*S, H]  fp32
__device__ __align__(16) __half g_xcat [(size_t)M_ROWS * KEFF];   // [M, 2K] = [hi|lo]
__device__ __align__(16) __half g_ccat [(size_t)M_ROWS * KEFF];   // ctx split
__device__ __align__(16) __half g_wqcat[(size_t)QKV_N * KEFF];    // W_qkv^T: [N,2K]=[w|w]
__device__ __align__(16) __half g_wocat[(size_t)HID   * KEFF];    // W_o^T

// ---------------------------------------------------------------------------
// helpers
// ---------------------------------------------------------------------------
__device__ __forceinline__ uint32_t su32(const void* p) {
    uint32_t a;
    asm("{ .reg .u64 t; cvta.to.shared.u64 t, %1; cvt.u32.u64 %0, t; }" : "=r"(a) : "l"(p));
    return a;
}
__device__ __forceinline__ void cpasync16(uint32_t saddr, const void* gaddr) {
    asm volatile("cp.async.cg.shared.global [%0], [%1], 16;" :: "r"(saddr), "l"(gaddr));
}
__device__ __forceinline__ void ldm_x4(uint32_t* r, uint32_t addr) {
    asm volatile("ldmatrix.sync.aligned.m8n8.x4.shared.b16 {%0,%1,%2,%3}, [%4];"
                 : "=r"(r[0]), "=r"(r[1]), "=r"(r[2]), "=r"(r[3]) : "r"(addr));
}
__device__ __forceinline__ void mma16816(float* c, const uint32_t* a, uint32_t b0, uint32_t b1) {
    asm volatile(
        "mma.sync.aligned.m16n8k16.row.col.f32.f16.f16.f32 "
        "{%0,%1,%2,%3}, {%4,%5,%6,%7}, {%8,%9}, {%0,%1,%2,%3};"
        : "+f"(c[0]), "+f"(c[1]), "+f"(c[2]), "+f"(c[3])
        : "r"(a[0]), "r"(a[1]), "r"(a[2]), "r"(a[3]), "r"(b0), "r"(b1));
}

// ---------------------------------------------------------------------------
// Pack activations: fp32 [M, K] -> fp16 [M, 2K] as [hi | lo]
// ---------------------------------------------------------------------------
__global__ void pack_a(const float* __restrict__ in, __half* __restrict__ out, int Mr)
{
    const int idx = blockIdx.x * blockDim.x + threadIdx.x;       // over M*K/2
    if (idx >= Mr * (HID / 2)) return;
    const int row = idx / (HID / 2);
    const int k   = (idx % (HID / 2)) * 2;
    const float2 f = *(const float2*)(in + (size_t)row * HID + k);
    const __half hx = __float2half(f.x);
    const __half hy = __float2half(f.y);
    const __half lx = __float2half(f.x - __half2float(hx));
    const __half ly = __float2half(f.y - __half2float(hy));
    __half* base = out + (size_t)row * KEFF;
    *(__half2*)(base + k)       = __halves2half2(hx, hy);
    *(__half2*)(base + HID + k) = __halves2half2(lx, ly);
}

// ---------------------------------------------------------------------------
// Pack weights: fp32 [K, N] -> fp16 transposed [N, 2K] as [w | w]
// ---------------------------------------------------------------------------
__global__ void pack_w(const float* __restrict__ in, __half* __restrict__ outT, int N)
{
    __shared__ float t[32][33];
    const int nb = blockIdx.x * 32, kb = blockIdx.y * 32;
    const int tx = threadIdx.x, ty = threadIdx.y;
#pragma unroll
    for (int i = 0; i < 32; i += 8)
        t[ty + i][tx] = in[(size_t)(kb + ty + i) * N + nb + tx];
    __syncthreads();
#pragma unroll
    for (int i = 0; i < 32; i += 8) {
        const float f = t[tx][ty + i];                 // = in[kb+tx][nb+ty+i]
        const __half h = __float2half(f);
        const int n = nb + ty + i, k = kb + tx;
        __half* base = outT + (size_t)n * KEFF;
        base[k]       = h;
        base[HID + k] = h;
    }
}

// ---------------------------------------------------------------------------
// fp16 mma.sync GEMM: C[M,Nd] = A'[M,Keff] @ B'[Nd,Keff]^T + bias
// 128x128 CTA tile, BK=32, 4-stage cp.async, 8 warps (4M x 2N), warp 32x64.
// smem rows padded to 80B (40 halves) -> conflict-free ldmatrix.
// ---------------------------------------------------------------------------
#define GSTG        4
#define TILE_BYTES  10240u                /* 128 rows x 80B */
#define SLOT_BYTES  (2u * TILE_BYTES)     /* A + B */
#define GEMM_DSMEM  (GSTG * SLOT_BYTES)   /* 81920 */

__global__ __launch_bounds__(256, 2)
void gemm_f16s(const __half* __restrict__ A, const __half* __restrict__ B,
               const float* __restrict__ bias, float* __restrict__ C, int Nd)
{
    extern __shared__ char smraw[];
    const uint32_t sbase = su32(smraw);

    const int tid  = threadIdx.x;
    const int lane = tid & 31, wid = tid >> 5;
    const int wm = (wid & 3) * 32, wn = (wid >> 2) * 64;
    const int m0 = blockIdx.y * 128, n0 = blockIdx.x * 128;
    const int nk = KEFF / 32;

    const __half* Ag = A + (size_t)m0 * KEFF;
    const __half* Bg = B + (size_t)n0 * KEFF;

    const int lrow = tid >> 2;                       // 0..63
    const int lcol = (tid & 3) * 8;                  // elem offset 0,8,16,24
    const uint32_t srowb = (uint32_t)lrow * 80u + (uint32_t)(tid & 3) * 16u;

    const uint32_t aBase = (uint32_t)(wm + (lane & 15)) * 80u + (uint32_t)(lane >> 4) * 16u;
    const uint32_t bBase = (uint32_t)(wn + (lane & 15)) * 80u + (uint32_t)(lane >> 4) * 16u;

    float c[2][8][4];
#pragma unroll
    for (int i = 0; i < 2; i++)
#pragma unroll
        for (int j = 0; j < 8; j++)
#pragma unroll
            for (int q = 0; q < 4; q++) c[i][j][q] = 0.f;

#define G_ISSUE(KT, SLOT) do {                                                     \
        if ((KT) < nk) {                                                           \
            const uint32_t sa = sbase + (uint32_t)(SLOT) * SLOT_BYTES;             \
            const uint32_t sb = sa + TILE_BYTES;                                   \
            const __half* ga = Ag + (size_t)lrow * KEFF + (KT) * 32 + lcol;        \
            const __half* gb = Bg + (size_t)lrow * KEFF + (KT) * 32 + lcol;        \
            cpasync16(sa + srowb,               ga);                               \
            cpasync16(sa + srowb + 64u * 80u,   ga + (size_t)64 * KEFF);           \
            cpasync16(sb + srowb,               gb);                               \
            cpasync16(sb + srowb + 64u * 80u,   gb + (size_t)64 * KEFF);           \
        }                                                                          \
        asm volatile("cp.async.commit_group;" ::: "memory");                       \
    } while (0)

    G_ISSUE(0, 0);
    G_ISSUE(1, 1);
    G_ISSUE(2, 2);

#pragma unroll 1
    for (int kt = 0; kt < nk; kt++) {
        asm volatile("cp.async.wait_group 2;" ::: "memory");
        __syncthreads();
        G_ISSUE(kt + 3, (kt + 3) & 3);

        const uint32_t sa = sbase + (uint32_t)(kt & 3) * SLOT_BYTES;
        const uint32_t sb = sa + TILE_BYTES;
#pragma unroll
        for (int kk = 0; kk < 2; kk++) {
            uint32_t A0[4], A1[4];
            ldm_x4(A0, sa + aBase + kk * 32u);
            ldm_x4(A1, sa + aBase + 1280u + kk * 32u);   // +16 rows
#pragma unroll
            for (int p = 0; p < 4; p++) {
                uint32_t Bq[4];
                ldm_x4(Bq, sb + bBase + (uint32_t)p * 1280u + kk * 32u);
                mma16816(c[0][2 * p],     A0, Bq[0], Bq[2]);
                mma16816(c[0][2 * p + 1], A0, Bq[1], Bq[3]);
                mma16816(c[1][2 * p],     A1, Bq[0], Bq[2]);
                mma16816(c[1][2 * p + 1], A1, Bq[1], Bq[3]);
            }
        }
    }
#undef G_ISSUE

    // epilogue: add bias, store fp32
    const int gg = lane >> 2, tt = (lane & 3) * 2;
#pragma unroll
    for (int nt = 0; nt < 8; nt++) {
        const int col = n0 + wn + nt * 8 + tt;
        const float2 bb = *(const float2*)(bias + col);
#pragma unroll
        for (int mt = 0; mt < 2; mt++) {
            const int row = m0 + wm + mt * 16 + gg;
            float2 v0, v1;
            v0.x = c[mt][nt][0] + bb.x;  v0.y = c[mt][nt][1] + bb.y;
            v1.x = c[mt][nt][2] + bb.x;  v1.y = c[mt][nt][3] + bb.y;
            *(float2*)(C + (size_t)row * Nd + col)       = v0;
            *(float2*)(C + (size_t)(row + 8) * Nd + col) = v1;
        }
    }
}

// ---------------------------------------------------------------------------
// Flash attention fp32, v2:
//  - PV: 8 rows x 4 cols per thread (warp-broadcast p loads, FFMA-bound)
//  - softmax: 4 threads per row with shuffle reductions
//  - 2 blocks/SM
// ---------------------------------------------------------------------------
#define FLASH_SMEM_FLOATS (3 * 64 * 132 + 64 * 65 + 3 * 64)
#define FLASH_SMEM_BYTES  (FLASH_SMEM_FLOATS * 4)

__global__ __launch_bounds__(256, 2)
void flash_attn(const float* __restrict__ qkv, float* __restrict__ ctx)
{
    extern __shared__ float sm[];
    float* Qs   = sm;                   // [64][132]
    float* Ks   = Qs + 64 * 132;        // [64][132]
    float* Vs   = Ks + 64 * 132;        // [64][132]
    float* Ss   = Vs + 64 * 132;        // [64][65]
    float* mrow = Ss + 64 * 65;         // [64]
    float* lrow = mrow + 64;            // [64]
    float* arow = lrow + 64;            // [64]

    const int tid = threadIdx.x;
    const int bh  = blockIdx.y;
    const int b   = bh >> 5;
    const int h   = bh & 31;
    const int qb  = blockIdx.x;
    const float scale = 0.088388347648318447f;   // 1/sqrt(128)

    const float* base = qkv + (size_t)b * S_LEN * QKV_N + (size_t)h * HD;
    const float* qg = base + (size_t)(qb * 64) * QKV_N;
    const float* kg = base + HID;
    const float* vg = base + 2 * HID;

    for (int i = tid; i < 64 * 32; i += 256) {
        const int r = i >> 5;
        const int c = (i & 31) << 2;
        *(float4*)&Qs[r * 132 + c] = *(const float4*)(qg + (size_t)r * QKV_N + c);
    }
    if (tid < 64) { mrow[tid] = NEG_BIG; lrow[tid] = 0.f; }

    float acc[8][4];
#pragma unroll
    for (int i = 0; i < 8; i++)
#pragma unroll
        for (int j = 0; j < 4; j++) acc[i][j] = 0.f;

    const int sy = tid >> 4, sx = tid & 15;      // score: 4 rows x 4 cols
    const int smr = tid >> 2, sms = tid & 3;     // softmax: 4 threads per row
    const int rg = tid >> 5, cg = tid & 31;      // PV: 8 rows x 4 cols

    __syncthreads();

    for (int j = 0; j < S_LEN / 64; ++j) {
        // Load K,V tiles [64][128]
        for (int i = tid; i < 64 * 32; i += 256) {
            const int r = i >> 5;
            const int c = (i & 31) << 2;
            const size_t go = (size_t)(j * 64 + r) * QKV_N + c;
            *(float4*)&Ks[r * 132 + c] = *(const float4*)(kg + go);
            *(float4*)&Vs[r * 132 + c] = *(const float4*)(vg + go);
        }
        __syncthreads();

        // Scores: s[r][c] = q[r] . k[c], 4x4 per thread
        float s[4][4];
#pragma unroll
        for (int i = 0; i < 4; i++)
#pragma unroll
            for (int c = 0; c < 4; c++) s[i][c] = 0.f;
#pragma unroll 4
        for (int d = 0; d < HD; d += 4) {
            float4 qv[4], kv[4];
#pragma unroll
            for (int i = 0; i < 4; i++) qv[i] = *(const float4*)&Qs[(sy * 4 + i) * 132 + d];
#pragma unroll
            for (int c = 0; c < 4; c++) kv[c] = *(const float4*)&Ks[(sx * 4 + c) * 132 + d];
#pragma unroll
            for (int i = 0; i < 4; i++)
#pragma unroll
                for (int c = 0; c < 4; c++)
                    s[i][c] += qv[i].x * kv[c].x + qv[i].y * kv[c].y
                             + qv[i].z * kv[c].z + qv[i].w * kv[c].w;
        }
#pragma unroll
        for (int i = 0; i < 4; i++)
#pragma unroll
            for (int c = 0; c < 4; c++)
                Ss[(sy * 4 + i) * 65 + sx * 4 + c] = s[i][c] * scale;
        __syncthreads();

        // Online softmax: 4 threads per row, 16 cols each
        {
            const float mold = mrow[smr];
            float* row = &Ss[smr * 65 + sms * 16];
            float mt = mold;
#pragma unroll
            for (int c = 0; c < 16; c++) mt = fmaxf(mt, row[c]);
            mt = fmaxf(mt, __shfl_xor_sync(0xffffffffu, mt, 1));
            mt = fmaxf(mt, __shfl_xor_sync(0xffffffffu, mt, 2));
            float lt = 0.f;
#pragma unroll
            for (int c = 0; c < 16; c++) {
                const float p = __expf(row[c] - mt);
                row[c] = p;
                lt += p;
            }
            lt += __shfl_xor_sync(0xffffffffu, lt, 1);
            lt += __shfl_xor_sync(0xffffffffu, lt, 2);
            if (sms == 0) {
                const float alpha = __expf(mold - mt);
                arow[smr] = alpha;
                lrow[smr] = lrow[smr] * alpha + lt;
                mrow[smr] = mt;
            }
        }
        __syncthreads();

        // acc = acc*alpha + P @ V   (8 rows x 4 cols per thread)
#pragma unroll
        for (int i = 0; i < 8; i++) {
            const float al = arow[rg * 8 + i];
#pragma unroll
            for (int q = 0; q < 4; q++) acc[i][q] *= al;
        }
#pragma unroll 4
        for (int c = 0; c < 64; c++) {
            const float4 vv = *(const float4*)&Vs[c * 132 + cg * 4];
#pragma unroll
            for (int i = 0; i < 8; i++) {
                const float p = Ss[(rg * 8 + i) * 65 + c];
                acc[i][0] += p * vv.x;
                acc[i][1] += p * vv.y;
                acc[i][2] += p * vv.z;
                acc[i][3] += p * vv.w;
            }
        }
        __syncthreads();
    }

    // Epilogue
#pragma unroll
    for (int i = 0; i < 8; i++) {
        const int r = rg * 8 + i;
        const float invl = 1.f / lrow[r];
        float4 o;
        o.x = acc[i][0] * invl;
        o.y = acc[i][1] * invl;
        o.z = acc[i][2] * invl;
        o.w = acc[i][3] * invl;
        *(float4*)(ctx + (size_t)(b * S_LEN + qb * 64 + r) * HID + h * HD + cg * 4) = o;
    }
}

// ---------------------------------------------------------------------------
// Host side
// ---------------------------------------------------------------------------
extern "C" void kernel_launch(void* const* d_in, const int* in_sizes, int n_in,
                              void* d_out, int out_size)
{
    (void)in_sizes; (void)n_in; (void)out_size;
    const float* x    = (const float*)d_in[0];
    const float* qkvw = (const float*)d_in[1];
    const float* qkvb = (const float*)d_in[2];
    const float* ow   = (const float*)d_in[3];
    const float* ob   = (const float*)d_in[4];
    float* out = (float*)d_out;

    float *qkv, *ctx;
    __half *xcat, *ccat, *wqcat, *wocat;
    cudaGetSymbolAddress((void**)&qkv,   g_qkv);
    cudaGetSymbolAddress((void**)&ctx,   g_ctx);
    cudaGetSymbolAddress((void**)&xcat,  g_xcat);
    cudaGetSymbolAddress((void**)&ccat,  g_ccat);
    cudaGetSymbolAddress((void**)&wqcat, g_wqcat);
    cudaGetSymbolAddress((void**)&wocat, g_wocat);

    cudaFuncSetAttribute(gemm_f16s, cudaFuncAttributeMaxDynamicSharedMemorySize, GEMM_DSMEM);
    cudaFuncSetAttribute(flash_attn, cudaFuncAttributeMaxDynamicSharedMemorySize, FLASH_SMEM_BYTES);

    const int napack = M_ROWS * (HID / 2);

    // 1) pack x and W_qkv
    pack_a<<<(napack + 255) / 256, 256>>>(x, xcat, M_ROWS);
    pack_w<<<dim3(QKV_N / 32, HID / 32), dim3(32, 8)>>>(qkvw, wqcat, QKV_N);

    // 2) QKV = x @ W_qkv + b   (fp16 2-term split mma.sync)
    gemm_f16s<<<dim3(QKV_N / 128, M_ROWS / 128), 256, GEMM_DSMEM>>>(
        xcat, wqcat, qkvb, qkv, QKV_N);

    // 3) attention
    flash_attn<<<dim3(S_LEN / 64, BATCH * NHEADS), 256, FLASH_SMEM_BYTES>>>(qkv, ctx);

    // 4) pack ctx and W_o
    pack_a<<<(napack + 255) / 256, 256>>>(ctx, ccat, M_ROWS);
    pack_w<<<dim3(HID / 32, HID / 32), dim3(32, 8)>>>(ow, wocat, HID);

    // 5) out = ctx @ W_o + b
    gemm_f16s<<<dim3(HID / 128, M_ROWS / 128), 256, GEMM_DSMEM>>>(
        ccat, wocat, ob, out, HID);
}

// round 8
// speedup vs baseline: 7.9950x; 2.5066x over previous
#include <cuda_runtime.h>
#include <cuda_fp16.h>
#include <math.h>
#include <stdint.h>

#define S_LEN   2048
#define BATCH   2
#define HID     4096
#define NHEADS  32
#define HD      128
#define M_ROWS  (BATCH * S_LEN)     /* 4096 */
#define QKV_N   (3 * HID)           /* 12288 */
#define KEFF    (2 * HID)           /* 8192 = doubled K for fp16 2-term split */
#define NEG_BIG (-1e30f)
#define SM_SCALE 0.088388347648318447f   /* 1/sqrt(128), folded into Q */

// ---------------------------------------------------------------------------
// Scratch (allocation-free rule: __device__ globals)
// ---------------------------------------------------------------------------
__device__ __align__(16) __half g_qf[(size_t)BATCH * NHEADS * S_LEN * HD];  // [b,h,s,d] scaled
__device__ __align__(16) __half g_kf[(size_t)BATCH * NHEADS * S_LEN * HD];
__device__ __align__(16) __half g_vf[(size_t)BATCH * NHEADS * S_LEN * HD];
__device__ __align__(16) __half g_xcat [(size_t)M_ROWS * KEFF];   // [M, 2K] = [hi|lo]
__device__ __align__(16) __half g_ccat [(size_t)M_ROWS * KEFF];   // ctx hi|lo (written by flash)
__device__ __align__(16) __half g_wqcat[(size_t)QKV_N * KEFF];    // W_qkv^T: [N,2K]=[w|w]
__device__ __align__(16) __half g_wocat[(size_t)HID   * KEFF];    // W_o^T

// ---------------------------------------------------------------------------
// helpers
// ---------------------------------------------------------------------------
__device__ __forceinline__ uint32_t su32(const void* p) {
    uint32_t a;
    asm("{ .reg .u64 t; cvta.to.shared.u64 t, %1; cvt.u32.u64 %0, t; }" : "=r"(a) : "l"(p));
    return a;
}
__device__ __forceinline__ void cpasync16(uint32_t saddr, const void* gaddr) {
    asm volatile("cp.async.cg.shared.global [%0], [%1], 16;" :: "r"(saddr), "l"(gaddr));
}
__device__ __forceinline__ void ldm_x4(uint32_t* r, uint32_t addr) {
    asm volatile("ldmatrix.sync.aligned.m8n8.x4.shared.b16 {%0,%1,%2,%3}, [%4];"
                 : "=r"(r[0]), "=r"(r[1]), "=r"(r[2]), "=r"(r[3]) : "r"(addr));
}
__device__ __forceinline__ void ldm_x4t(uint32_t* r, uint32_t addr) {
    asm volatile("ldmatrix.sync.aligned.m8n8.x4.trans.shared.b16 {%0,%1,%2,%3}, [%4];"
                 : "=r"(r[0]), "=r"(r[1]), "=r"(r[2]), "=r"(r[3]) : "r"(addr));
}
__device__ __forceinline__ void mma16816(float* c, const uint32_t* a, uint32_t b0, uint32_t b1) {
    asm volatile(
        "mma.sync.aligned.m16n8k16.row.col.f32.f16.f16.f32 "
        "{%0,%1,%2,%3}, {%4,%5,%6,%7}, {%8,%9}, {%0,%1,%2,%3};"
        : "+f"(c[0]), "+f"(c[1]), "+f"(c[2]), "+f"(c[3])
        : "r"(a[0]), "r"(a[1]), "r"(a[2]), "r"(a[3]), "r"(b0), "r"(b1));
}
__device__ __forceinline__ uint32_t packh2(float a, float b) {
    __half2 h = __floats2half2_rn(a, b);
    return *(uint32_t*)&h;
}

// ---------------------------------------------------------------------------
// Pack activations: fp32 [M, K] -> fp16 [M, 2K] as [hi | lo]
// ---------------------------------------------------------------------------
__global__ void pack_a(const float* __restrict__ in, __half* __restrict__ out, int Mr)
{
    const int idx = blockIdx.x * blockDim.x + threadIdx.x;
    if (idx >= Mr * (HID / 2)) return;
    const int row = idx / (HID / 2);
    const int k   = (idx % (HID / 2)) * 2;
    const float2 f = *(const float2*)(in + (size_t)row * HID + k);
    const __half hx = __float2half(f.x);
    const __half hy = __float2half(f.y);
    const __half lx = __float2half(f.x - __half2float(hx));
    const __half ly = __float2half(f.y - __half2float(hy));
    __half* base = out + (size_t)row * KEFF;
    *(__half2*)(base + k)       = __halves2half2(hx, hy);
    *(__half2*)(base + HID + k) = __halves2half2(lx, ly);
}

// ---------------------------------------------------------------------------
// Pack weights: fp32 [K, N] -> fp16 transposed [N, 2K] as [w | w]
// ---------------------------------------------------------------------------
__global__ void pack_w(const float* __restrict__ in, __half* __restrict__ outT, int N)
{
    __shared__ float t[32][33];
    const int nb = blockIdx.x * 32, kb = blockIdx.y * 32;
    const int tx = threadIdx.x, ty = threadIdx.y;
#pragma unroll
    for (int i = 0; i < 32; i += 8)
        t[ty + i][tx] = in[(size_t)(kb + ty + i) * N + nb + tx];
    __syncthreads();
#pragma unroll
    for (int i = 0; i < 32; i += 8) {
        const float f = t[tx][ty + i];
        const __half h = __float2half(f);
        const int n = nb + ty + i, k = kb + tx;
        __half* base = outT + (size_t)n * KEFF;
        base[k]       = h;
        base[HID + k] = h;
    }
}

// ---------------------------------------------------------------------------
// fp16 mma.sync GEMM: 128x128 CTA tile, BK=32, 4-stage cp.async, 8 warps.
// MODE 0: C = A'B'^T + bias (fp32 store).
// MODE 1: qkv epilogue -> fp16 [b,h,s,d] buffers, Q scaled by SM_SCALE.
// ---------------------------------------------------------------------------
#define GSTG        4
#define TILE_BYTES  10240u
#define SLOT_BYTES  (2u * TILE_BYTES)
#define GEMM_DSMEM  (GSTG * SLOT_BYTES)

template<int MODE>
__global__ __launch_bounds__(256, 2)
void gemm_f16s(const __half* __restrict__ A, const __half* __restrict__ B,
               const float* __restrict__ bias, float* __restrict__ C, int Nd,
               __half* __restrict__ qf, __half* __restrict__ kf, __half* __restrict__ vf)
{
    extern __shared__ char smraw[];
    const uint32_t sbase = su32(smraw);

    const int tid  = threadIdx.x;
    const int lane = tid & 31, wid = tid >> 5;
    const int wm = (wid & 3) * 32, wn = (wid >> 2) * 64;
    const int m0 = blockIdx.y * 128, n0 = blockIdx.x * 128;
    const int nk = KEFF / 32;

    const __half* Ag = A + (size_t)m0 * KEFF;
    const __half* Bg = B + (size_t)n0 * KEFF;

    const int lrow = tid >> 2;
    const int lcol = (tid & 3) * 8;
    const uint32_t srowb = (uint32_t)lrow * 80u + (uint32_t)(tid & 3) * 16u;

    const uint32_t aBase = (uint32_t)(wm + (lane & 15)) * 80u + (uint32_t)(lane >> 4) * 16u;
    const uint32_t bBase = (uint32_t)(wn + (lane & 15)) * 80u + (uint32_t)(lane >> 4) * 16u;

    float c[2][8][4];
#pragma unroll
    for (int i = 0; i < 2; i++)
#pragma unroll
        for (int j = 0; j < 8; j++)
#pragma unroll
            for (int q = 0; q < 4; q++) c[i][j][q] = 0.f;

#define G_ISSUE(KT, SLOT) do {                                                     \
        if ((KT) < nk) {                                                           \
            const uint32_t sa = sbase + (uint32_t)(SLOT) * SLOT_BYTES;             \
            const uint32_t sb = sa + TILE_BYTES;                                   \
            const __half* ga = Ag + (size_t)lrow * KEFF + (KT) * 32 + lcol;        \
            const __half* gb = Bg + (size_t)lrow * KEFF + (KT) * 32 + lcol;        \
            cpasync16(sa + srowb,               ga);                               \
            cpasync16(sa + srowb + 64u * 80u,   ga + (size_t)64 * KEFF);           \
            cpasync16(sb + srowb,               gb);                               \
            cpasync16(sb + srowb + 64u * 80u,   gb + (size_t)64 * KEFF);           \
        }                                                                          \
        asm volatile("cp.async.commit_group;" ::: "memory");                       \
    } while (0)

    G_ISSUE(0, 0);
    G_ISSUE(1, 1);
    G_ISSUE(2, 2);

#pragma unroll 1
    for (int kt = 0; kt < nk; kt++) {
        asm volatile("cp.async.wait_group 2;" ::: "memory");
        __syncthreads();
        G_ISSUE(kt + 3, (kt + 3) & 3);

        const uint32_t sa = sbase + (uint32_t)(kt & 3) * SLOT_BYTES;
        const uint32_t sb = sa + TILE_BYTES;
#pragma unroll
        for (int kk = 0; kk < 2; kk++) {
            uint32_t A0[4], A1[4];
            ldm_x4(A0, sa + aBase + kk * 32u);
            ldm_x4(A1, sa + aBase + 1280u + kk * 32u);
#pragma unroll
            for (int p = 0; p < 4; p++) {
                uint32_t Bq[4];
                ldm_x4(Bq, sb + bBase + (uint32_t)p * 1280u + kk * 32u);
                mma16816(c[0][2 * p],     A0, Bq[0], Bq[2]);
                mma16816(c[0][2 * p + 1], A0, Bq[1], Bq[3]);
                mma16816(c[1][2 * p],     A1, Bq[0], Bq[2]);
                mma16816(c[1][2 * p + 1], A1, Bq[1], Bq[3]);
            }
        }
    }
#undef G_ISSUE

    const int gg = lane >> 2, tt = (lane & 3) * 2;

    if (MODE == 0) {
#pragma unroll
        for (int nt = 0; nt < 8; nt++) {
            const int col = n0 + wn + nt * 8 + tt;
            const float2 bb = *(const float2*)(bias + col);
#pragma unroll
            for (int mt = 0; mt < 2; mt++) {
                const int row = m0 + wm + mt * 16 + gg;
                float2 v0, v1;
                v0.x = c[mt][nt][0] + bb.x;  v0.y = c[mt][nt][1] + bb.y;
                v1.x = c[mt][nt][2] + bb.x;  v1.y = c[mt][nt][3] + bb.y;
                *(float2*)(C + (size_t)row * Nd + col)       = v0;
                *(float2*)(C + (size_t)(row + 8) * Nd + col) = v1;
            }
        }
    } else {
        // qkv epilogue: block covers exactly one segment (q/k/v) and one head.
        const int seg = n0 >> 12;               // 0=q, 1=k, 2=v
        const int h   = (n0 >> 7) & 31;
        __half* dst = (seg == 0) ? qf : (seg == 1) ? kf : vf;
        const float sc = (seg == 0) ? SM_SCALE : 1.0f;
#pragma unroll
        for (int nt = 0; nt < 8; nt++) {
            const int col = n0 + wn + nt * 8 + tt;
            const int d   = wn + nt * 8 + tt;
            const float2 bb = *(const float2*)(bias + col);
#pragma unroll
            for (int mt = 0; mt < 2; mt++) {
                const int row = m0 + wm + mt * 16 + gg;     // token
#pragma unroll
                for (int half8 = 0; half8 < 2; half8++) {
                    const int tok = row + half8 * 8;
                    const int b = tok >> 11, s = tok & 2047;
                    const float v0 = (c[mt][nt][2 * half8 + 0] + bb.x) * sc;
                    const float v1 = (c[mt][nt][2 * half8 + 1] + bb.y) * sc;
                    __half2* p = (__half2*)(dst + (((size_t)(b * NHEADS + h) * S_LEN + s) * HD + d));
                    *p = __floats2half2_rn(v0, v1);
                }
            }
        }
    }
}

// ---------------------------------------------------------------------------
// Tensor-core flash attention (fp16 in, fp32 acc):
// Br=128 (8 warps x 16 q-rows), Bc=64. Each warp owns full rows -> register
// softmax with 4-lane shuffles. Writes ctx as fp16 hi|lo into ccat [M, 2H].
// ---------------------------------------------------------------------------
#define QROW 272                     /* 128 halves + 8 pad, bytes */
#define FL_SMEM (128 * QROW + 64 * QROW + 64 * QROW)   /* 69632 */

__global__ __launch_bounds__(256, 2)
void flash_mma(const __half* __restrict__ Qf, const __half* __restrict__ Kf,
               const __half* __restrict__ Vf, __half* __restrict__ ccat)
{
    extern __shared__ char sm8[];
    const uint32_t qs = su32(sm8);
    const uint32_t ks = qs + 128 * QROW;
    const uint32_t vs = ks + 64 * QROW;

    const int tid = threadIdx.x, lane = tid & 31, wid = tid >> 5;
    const int bh = blockIdx.y, qb = blockIdx.x;
    const int g = lane >> 2, t = lane & 3;

    const __half* qg = Qf + ((size_t)bh * S_LEN + qb * 128) * HD;
    const __half* kg = Kf + (size_t)bh * S_LEN * HD;
    const __half* vg = Vf + (size_t)bh * S_LEN * HD;

    // Load Q tile [128][128]
    for (int i = tid; i < 2048; i += 256) {
        const int r = i >> 4, cc = i & 15;
        cpasync16(qs + r * QROW + cc * 16, qg + (size_t)r * HD + cc * 8);
    }
    asm volatile("cp.async.commit_group;" ::: "memory");

    float acc[16][4];
#pragma unroll
    for (int i = 0; i < 16; i++)
#pragma unroll
        for (int q = 0; q < 4; q++) acc[i][q] = 0.f;
    float m0 = NEG_BIG, m1 = NEG_BIG, l0 = 0.f, l1 = 0.f;

    const uint32_t aB = qs + (uint32_t)(wid * 16 + (lane & 15)) * QROW + (uint32_t)(lane >> 4) * 16u;
    const uint32_t bB = ks + (uint32_t)(lane & 15) * QROW + (uint32_t)(lane >> 4) * 16u;
    const uint32_t vB = vs + (uint32_t)(lane & 15) * QROW + (uint32_t)(lane >> 4) * 16u;

    asm volatile("cp.async.wait_group 0;" ::: "memory");
    __syncthreads();

#pragma unroll 1
    for (int j = 0; j < S_LEN / 64; j++) {
        // Load K,V tile [64][128]
        for (int i = tid; i < 1024; i += 256) {
            const int r = i >> 4, cc = i & 15;
            const size_t go = (size_t)(j * 64 + r) * HD + cc * 8;
            cpasync16(ks + r * QROW + cc * 16, kg + go);
            cpasync16(vs + r * QROW + cc * 16, vg + go);
        }
        asm volatile("cp.async.commit_group;" ::: "memory");
        asm volatile("cp.async.wait_group 0;" ::: "memory");
        __syncthreads();

        // Scores: S16x64 per warp (Q pre-scaled). cs frag j: keys (j>>1)*16 + (j&1)*8 + ...
        float cs[8][4];
#pragma unroll
        for (int i = 0; i < 8; i++)
#pragma unroll
            for (int q = 0; q < 4; q++) cs[i][q] = 0.f;
#pragma unroll
        for (int kd = 0; kd < 8; kd++) {
            uint32_t Aq[4];
            ldm_x4(Aq, aB + kd * 32u);
#pragma unroll
            for (int p = 0; p < 4; p++) {
                uint32_t Bq[4];
                ldm_x4(Bq, bB + (uint32_t)p * 16u * QROW + kd * 32u);
                mma16816(cs[2 * p],     Aq, Bq[0], Bq[2]);
                mma16816(cs[2 * p + 1], Aq, Bq[1], Bq[3]);
            }
        }

        // Online softmax (rows g and g+8)
        float rm0 = m0, rm1 = m1;
#pragma unroll
        for (int i = 0; i < 8; i++) {
            rm0 = fmaxf(rm0, fmaxf(cs[i][0], cs[i][1]));
            rm1 = fmaxf(rm1, fmaxf(cs[i][2], cs[i][3]));
        }
        rm0 = fmaxf(rm0, __shfl_xor_sync(0xffffffffu, rm0, 1));
        rm0 = fmaxf(rm0, __shfl_xor_sync(0xffffffffu, rm0, 2));
        rm1 = fmaxf(rm1, __shfl_xor_sync(0xffffffffu, rm1, 1));
        rm1 = fmaxf(rm1, __shfl_xor_sync(0xffffffffu, rm1, 2));
        const float al0 = __expf(m0 - rm0);
        const float al1 = __expf(m1 - rm1);
        m0 = rm0; m1 = rm1;

        uint32_t ph[8][2];
        float s0 = 0.f, s1 = 0.f;
#pragma unroll
        for (int i = 0; i < 8; i++) {
            const float e0 = __expf(cs[i][0] - m0);
            const float e1 = __expf(cs[i][1] - m0);
            const float e2 = __expf(cs[i][2] - m1);
            const float e3 = __expf(cs[i][3] - m1);
            s0 += e0 + e1;  s1 += e2 + e3;
            ph[i][0] = packh2(e0, e1);
            ph[i][1] = packh2(e2, e3);
        }
        s0 += __shfl_xor_sync(0xffffffffu, s0, 1);
        s0 += __shfl_xor_sync(0xffffffffu, s0, 2);
        s1 += __shfl_xor_sync(0xffffffffu, s1, 1);
        s1 += __shfl_xor_sync(0xffffffffu, s1, 2);
        l0 = l0 * al0 + s0;
        l1 = l1 * al1 + s1;

#pragma unroll
        for (int i = 0; i < 16; i++) {
            acc[i][0] *= al0; acc[i][1] *= al0;
            acc[i][2] *= al1; acc[i][3] *= al1;
        }

        // acc += P @ V  (V^T via ldmatrix.trans)
#pragma unroll
        for (int kc = 0; kc < 4; kc++) {
            uint32_t Ap[4] = { ph[2 * kc][0], ph[2 * kc][1], ph[2 * kc + 1][0], ph[2 * kc + 1][1] };
#pragma unroll
            for (int dn = 0; dn < 8; dn++) {
                uint32_t Bv[4];
                ldm_x4t(Bv, vB + (uint32_t)kc * 16u * QROW + (uint32_t)dn * 32u);
                mma16816(acc[2 * dn],     Ap, Bv[0], Bv[1]);
                mma16816(acc[2 * dn + 1], Ap, Bv[2], Bv[3]);
            }
        }
        __syncthreads();
    }

    // Epilogue: ctx -> ccat [token][hi: h*128+d | lo: 4096 + h*128+d]
    const float il0 = 1.f / l0, il1 = 1.f / l1;
    const int b = bh >> 5, h = bh & 31;
    const int tok0 = b * S_LEN + qb * 128 + wid * 16 + g;
#pragma unroll
    for (int nt = 0; nt < 16; nt++) {
        const int d0 = (nt >> 1) * 16 + (nt & 1) * 8 + 2 * t;
#pragma unroll
        for (int half8 = 0; half8 < 2; half8++) {
            const int tok = tok0 + half8 * 8;
            const float il = half8 ? il1 : il0;
            const float v0 = acc[nt][2 * half8 + 0] * il;
            const float v1 = acc[nt][2 * half8 + 1] * il;
            const __half h0 = __float2half(v0);
            const __half h1 = __float2half(v1);
            const __half q0 = __float2half(v0 - __half2float(h0));
            const __half q1 = __float2half(v1 - __half2float(h1));
            __half* base = ccat + (size_t)tok * KEFF + h * HD + d0;
            *(__half2*)base          = __halves2half2(h0, h1);
            *(__half2*)(base + HID)  = __halves2half2(q0, q1);
        }
    }
}

// ---------------------------------------------------------------------------
// Host side
// ---------------------------------------------------------------------------
extern "C" void kernel_launch(void* const* d_in, const int* in_sizes, int n_in,
                              void* d_out, int out_size)
{
    (void)in_sizes; (void)n_in; (void)out_size;
    const float* x    = (const float*)d_in[0];
    const float* qkvw = (const float*)d_in[1];
    const float* qkvb = (const float*)d_in[2];
    const float* ow   = (const float*)d_in[3];
    const float* ob   = (const float*)d_in[4];
    float* out = (float*)d_out;

    __half *qf, *kf, *vf, *xcat, *ccat, *wqcat, *wocat;
    cudaGetSymbolAddress((void**)&qf,    g_qf);
    cudaGetSymbolAddress((void**)&kf,    g_kf);
    cudaGetSymbolAddress((void**)&vf,    g_vf);
    cudaGetSymbolAddress((void**)&xcat,  g_xcat);
    cudaGetSymbolAddress((void**)&ccat,  g_ccat);
    cudaGetSymbolAddress((void**)&wqcat, g_wqcat);
    cudaGetSymbolAddress((void**)&wocat, g_wocat);

    cudaFuncSetAttribute(gemm_f16s<0>, cudaFuncAttributeMaxDynamicSharedMemorySize, GEMM_DSMEM);
    cudaFuncSetAttribute(gemm_f16s<1>, cudaFuncAttributeMaxDynamicSharedMemorySize, GEMM_DSMEM);
    cudaFuncSetAttribute(flash_mma, cudaFuncAttributeMaxDynamicSharedMemorySize, FL_SMEM);

    const int napack = M_ROWS * (HID / 2);

    // 1) pack x and W_qkv
    pack_a<<<(napack + 255) / 256, 256>>>(x, xcat, M_ROWS);
    pack_w<<<dim3(QKV_N / 32, HID / 32), dim3(32, 8)>>>(qkvw, wqcat, QKV_N);

    // 2) q,k,v (fp16, q pre-scaled) = x @ W_qkv + b
    gemm_f16s<1><<<dim3(QKV_N / 128, M_ROWS / 128), 256, GEMM_DSMEM>>>(
        xcat, wqcat, qkvb, nullptr, QKV_N, qf, kf, vf);

    // 3) tensor-core flash attention -> ccat (fp16 hi|lo)
    flash_mma<<<dim3(S_LEN / 128, BATCH * NHEADS), 256, FL_SMEM>>>(qf, kf, vf, ccat);

    // 4) pack W_o
    pack_w<<<dim3(HID / 32, HID / 32), dim3(32, 8)>>>(ow, wocat, HID);

    // 5) out = ctx @ W_o + b
    gemm_f16s<0><<<dim3(HID / 128, M_ROWS / 128), 256, GEMM_DSMEM>>>(
        ccat, wocat, ob, out, HID, nullptr, nullptr, nullptr);
}

// round 9
// speedup vs baseline: 8.4066x; 1.0515x over previous
#include <cuda_runtime.h>
#include <cuda_fp16.h>
#include <math.h>
#include <stdint.h>

#define S_LEN   2048
#define BATCH   2
#define HID     4096
#define NHEADS  32
#define HD      128
#define M_ROWS  (BATCH * S_LEN)     /* 4096 */
#define QKV_N   (3 * HID)           /* 12288 */
#define KEFF    (2 * HID)           /* 8192: xcat/ccat layout stride [hi|lo] */
#define NEG_BIG (-1e30f)
#define SM_SCALE 0.088388347648318447f   /* 1/sqrt(128), folded into Q */

// ---------------------------------------------------------------------------
// Scratch (allocation-free rule: __device__ globals)
// ---------------------------------------------------------------------------
__device__ __align__(16) __half g_qf[(size_t)BATCH * NHEADS * S_LEN * HD];  // [b,h,s,d] scaled
__device__ __align__(16) __half g_kf[(size_t)BATCH * NHEADS * S_LEN * HD];
__device__ __align__(16) __half g_vf[(size_t)BATCH * NHEADS * S_LEN * HD];
__device__ __align__(16) __half g_xcat [(size_t)M_ROWS * KEFF];   // [M, 2K] = [hi|lo]
__device__ __align__(16) __half g_ccat [(size_t)M_ROWS * KEFF];   // ctx hi|lo (from flash)
__device__ __align__(16) __half g_wq[(size_t)QKV_N * HID];        // W_qkv^T [N,K] fp16
__device__ __align__(16) __half g_wo[(size_t)HID   * HID];        // W_o^T   [N,K] fp16

// ---------------------------------------------------------------------------
// helpers
// ---------------------------------------------------------------------------
__device__ __forceinline__ uint32_t su32(const void* p) {
    uint32_t a;
    asm("{ .reg .u64 t; cvta.to.shared.u64 t, %1; cvt.u32.u64 %0, t; }" : "=r"(a) : "l"(p));
    return a;
}
__device__ __forceinline__ void cpasync16(uint32_t saddr, const void* gaddr) {
    asm volatile("cp.async.cg.shared.global [%0], [%1], 16;" :: "r"(saddr), "l"(gaddr));
}
__device__ __forceinline__ void ldm_x4(uint32_t* r, uint32_t addr) {
    asm volatile("ldmatrix.sync.aligned.m8n8.x4.shared.b16 {%0,%1,%2,%3}, [%4];"
                 : "=r"(r[0]), "=r"(r[1]), "=r"(r[2]), "=r"(r[3]) : "r"(addr));
}
__device__ __forceinline__ void ldm_x4t(uint32_t* r, uint32_t addr) {
    asm volatile("ldmatrix.sync.aligned.m8n8.x4.trans.shared.b16 {%0,%1,%2,%3}, [%4];"
                 : "=r"(r[0]), "=r"(r[1]), "=r"(r[2]), "=r"(r[3]) : "r"(addr));
}
__device__ __forceinline__ void mma16816(float* c, const uint32_t* a, uint32_t b0, uint32_t b1) {
    asm volatile(
        "mma.sync.aligned.m16n8k16.row.col.f32.f16.f16.f32 "
        "{%0,%1,%2,%3}, {%4,%5,%6,%7}, {%8,%9}, {%0,%1,%2,%3};"
        : "+f"(c[0]), "+f"(c[1]), "+f"(c[2]), "+f"(c[3])
        : "r"(a[0]), "r"(a[1]), "r"(a[2]), "r"(a[3]), "r"(b0), "r"(b1));
}
__device__ __forceinline__ uint32_t packh2(float a, float b) {
    __half2 h = __floats2half2_rn(a, b);
    return *(uint32_t*)&h;
}

// ---------------------------------------------------------------------------
// Pack activations: fp32 [M, K] -> fp16 [M, 2K] as [hi | lo]
// ---------------------------------------------------------------------------
__global__ void pack_a(const float* __restrict__ in, __half* __restrict__ out, int Mr)
{
    const int idx = blockIdx.x * blockDim.x + threadIdx.x;
    if (idx >= Mr * (HID / 2)) return;
    const int row = idx / (HID / 2);
    const int k   = (idx % (HID / 2)) * 2;
    const float2 f = *(const float2*)(in + (size_t)row * HID + k);
    const __half hx = __float2half(f.x);
    const __half hy = __float2half(f.y);
    const __half lx = __float2half(f.x - __half2float(hx));
    const __half ly = __float2half(f.y - __half2float(hy));
    __half* base = out + (size_t)row * KEFF;
    *(__half2*)(base + k)       = __halves2half2(hx, hy);
    *(__half2*)(base + HID + k) = __halves2half2(lx, ly);
}

// ---------------------------------------------------------------------------
// Pack weights: fp32 [K, N] -> fp16 transposed [N, K] (single copy)
// ---------------------------------------------------------------------------
__global__ void pack_w(const float* __restrict__ in, __half* __restrict__ outT, int N)
{
    __shared__ float t[32][33];
    const int nb = blockIdx.x * 32, kb = blockIdx.y * 32;
    const int tx = threadIdx.x, ty = threadIdx.y;
#pragma unroll
    for (int i = 0; i < 32; i += 8)
        t[ty + i][tx] = in[(size_t)(kb + ty + i) * N + nb + tx];
    __syncthreads();
#pragma unroll
    for (int i = 0; i < 32; i += 8) {
        const float f = t[tx][ty + i];
        outT[(size_t)(nb + ty + i) * HID + kb + tx] = __float2half(f);
    }
}

// ---------------------------------------------------------------------------
// fp16 split GEMM, shared-B formulation:
//   C[m][n] = sum_k (Ahi[m][k] + Alo[m][k]) * W[n][k]  (+ bias)
// 128x128 CTA tile over real K=4096, BK=32, stages hold {Ahi, Alo, B},
// 3-stage cp.async, 8 warps (4M x 2N), warp 32x64, both A-sets -> same acc.
// MODE 0: fp32 C + bias.   MODE 1: qkv epilogue -> fp16 [b,h,s,d].
// ---------------------------------------------------------------------------
#define GSTG        3
#define TILE_BYTES  10240u                 /* 128 rows x 80B */
#define SLOT_BYTES  (3u * TILE_BYTES)      /* Ahi + Alo + B */
#define GEMM_DSMEM  (GSTG * SLOT_BYTES)    /* 92160 */

template<int MODE>
__global__ __launch_bounds__(256, 2)
void gemm_f16s(const __half* __restrict__ A, const __half* __restrict__ B,
               const float* __restrict__ bias, float* __restrict__ C, int Nd,
               __half* __restrict__ qf, __half* __restrict__ kf, __half* __restrict__ vf)
{
    extern __shared__ char smraw[];
    const uint32_t sbase = su32(smraw);

    const int tid  = threadIdx.x;
    const int lane = tid & 31, wid = tid >> 5;
    const int wm = (wid & 3) * 32, wn = (wid >> 2) * 64;
    const int m0 = blockIdx.y * 128, n0 = blockIdx.x * 128;
    const int nk = HID / 32;                       /* 128 chunks */

    const __half* Ag = A + (size_t)m0 * KEFF;      /* hi at +0, lo at +HID */
    const __half* Bg = B + (size_t)n0 * HID;

    const int lrow = tid >> 2;                     /* 0..63 */
    const int lcol = (tid & 3) * 8;                /* halves: 0,8,16,24 */
    const uint32_t srowb = (uint32_t)lrow * 80u + (uint32_t)(tid & 3) * 16u;

    const uint32_t aBase = (uint32_t)(wm + (lane & 15)) * 80u + (uint32_t)(lane >> 4) * 16u;
    const uint32_t bBase = (uint32_t)(wn + (lane & 15)) * 80u + (uint32_t)(lane >> 4) * 16u;

    float c[2][8][4];
#pragma unroll
    for (int i = 0; i < 2; i++)
#pragma unroll
        for (int j = 0; j < 8; j++)
#pragma unroll
            for (int q = 0; q < 4; q++) c[i][j][q] = 0.f;

#define G_ISSUE(KT, SLOT) do {                                                     \
        if ((KT) < nk) {                                                           \
            const uint32_t st = sbase + (uint32_t)(SLOT) * SLOT_BYTES;             \
            const __half* gah = Ag + (size_t)lrow * KEFF + (KT) * 32 + lcol;       \
            const __half* gb  = Bg + (size_t)lrow * HID  + (KT) * 32 + lcol;       \
            cpasync16(st + srowb,                          gah);                   \
            cpasync16(st + srowb + 64u * 80u,              gah + (size_t)64 * KEFF);\
            cpasync16(st + TILE_BYTES + srowb,             gah + HID);             \
            cpasync16(st + TILE_BYTES + srowb + 64u * 80u, gah + HID + (size_t)64 * KEFF);\
            cpasync16(st + 2u * TILE_BYTES + srowb,             gb);               \
            cpasync16(st + 2u * TILE_BYTES + srowb + 64u * 80u, gb + (size_t)64 * HID);\
        }                                                                          \
        asm volatile("cp.async.commit_group;" ::: "memory");                       \
    } while (0)

    G_ISSUE(0, 0);
    G_ISSUE(1, 1);

    int slot = 0;
#pragma unroll 1
    for (int kt = 0; kt < nk; kt++) {
        asm volatile("cp.async.wait_group 1;" ::: "memory");
        __syncthreads();
        {
            const int ns = (slot + 2 >= GSTG) ? slot + 2 - GSTG : slot + 2;
            G_ISSUE(kt + 2, ns);
        }

        const uint32_t sa = sbase + (uint32_t)slot * SLOT_BYTES;        /* Ahi */
        const uint32_t sl = sa + TILE_BYTES;                            /* Alo */
        const uint32_t sb = sa + 2u * TILE_BYTES;                       /* B   */
#pragma unroll
        for (int kk = 0; kk < 2; kk++) {
            uint32_t A0h[4], A1h[4], A0l[4], A1l[4];
            ldm_x4(A0h, sa + aBase + kk * 32u);
            ldm_x4(A1h, sa + aBase + 1280u + kk * 32u);    /* +16 rows */
            ldm_x4(A0l, sl + aBase + kk * 32u);
            ldm_x4(A1l, sl + aBase + 1280u + kk * 32u);
#pragma unroll
            for (int p = 0; p < 4; p++) {
                uint32_t Bq[4];
                ldm_x4(Bq, sb + bBase + (uint32_t)p * 1280u + kk * 32u);
                mma16816(c[0][2 * p],     A0h, Bq[0], Bq[2]);
                mma16816(c[0][2 * p + 1], A0h, Bq[1], Bq[3]);
                mma16816(c[1][2 * p],     A1h, Bq[0], Bq[2]);
                mma16816(c[1][2 * p + 1], A1h, Bq[1], Bq[3]);
                mma16816(c[0][2 * p],     A0l, Bq[0], Bq[2]);
                mma16816(c[0][2 * p + 1], A0l, Bq[1], Bq[3]);
                mma16816(c[1][2 * p],     A1l, Bq[0], Bq[2]);
                mma16816(c[1][2 * p + 1], A1l, Bq[1], Bq[3]);
            }
        }
        slot = (slot + 1 >= GSTG) ? 0 : slot + 1;
    }
#undef G_ISSUE

    const int gg = lane >> 2, tt = (lane & 3) * 2;

    if (MODE == 0) {
#pragma unroll
        for (int nt = 0; nt < 8; nt++) {
            const int col = n0 + wn + nt * 8 + tt;
            const float2 bb = *(const float2*)(bias + col);
#pragma unroll
            for (int mt = 0; mt < 2; mt++) {
                const int row = m0 + wm + mt * 16 + gg;
                float2 v0, v1;
                v0.x = c[mt][nt][0] + bb.x;  v0.y = c[mt][nt][1] + bb.y;
                v1.x = c[mt][nt][2] + bb.x;  v1.y = c[mt][nt][3] + bb.y;
                *(float2*)(C + (size_t)row * Nd + col)       = v0;
                *(float2*)(C + (size_t)(row + 8) * Nd + col) = v1;
            }
        }
    } else {
        // qkv epilogue: block covers exactly one segment (q/k/v) and one head.
        const int seg = n0 >> 12;               /* 0=q, 1=k, 2=v */
        const int h   = (n0 >> 7) & 31;
        __half* dst = (seg == 0) ? qf : (seg == 1) ? kf : vf;
        const float sc = (seg == 0) ? SM_SCALE : 1.0f;
#pragma unroll
        for (int nt = 0; nt < 8; nt++) {
            const int col = n0 + wn + nt * 8 + tt;
            const int d   = wn + nt * 8 + tt;
            const float2 bb = *(const float2*)(bias + col);
#pragma unroll
            for (int mt = 0; mt < 2; mt++) {
                const int row = m0 + wm + mt * 16 + gg;
#pragma unroll
                for (int half8 = 0; half8 < 2; half8++) {
                    const int tok = row + half8 * 8;
                    const int b = tok >> 11, s = tok & 2047;
                    const float v0 = (c[mt][nt][2 * half8 + 0] + bb.x) * sc;
                    const float v1 = (c[mt][nt][2 * half8 + 1] + bb.y) * sc;
                    __half2* p = (__half2*)(dst + (((size_t)(b * NHEADS + h) * S_LEN + s) * HD + d));
                    *p = __floats2half2_rn(v0, v1);
                }
            }
        }
    }
}

// ---------------------------------------------------------------------------
// Tensor-core flash attention (unchanged from R8, known-good):
// Br=128 (8 warps x 16 q-rows), Bc=64, fp32 acc, fp16 hi|lo ctx output.
// ---------------------------------------------------------------------------
#define QROW 272
#define FL_SMEM (128 * QROW + 64 * QROW + 64 * QROW)   /* 69632 */

__global__ __launch_bounds__(256, 2)
void flash_mma(const __half* __restrict__ Qf, const __half* __restrict__ Kf,
               const __half* __restrict__ Vf, __half* __restrict__ ccat)
{
    extern __shared__ char sm8[];
    const uint32_t qs = su32(sm8);
    const uint32_t ks = qs + 128 * QROW;
    const uint32_t vs = ks + 64 * QROW;

    const int tid = threadIdx.x, lane = tid & 31, wid = tid >> 5;
    const int bh = blockIdx.y, qb = blockIdx.x;
    const int g = lane >> 2, t = lane & 3;

    const __half* qg = Qf + ((size_t)bh * S_LEN + qb * 128) * HD;
    const __half* kg = Kf + (size_t)bh * S_LEN * HD;
    const __half* vg = Vf + (size_t)bh * S_LEN * HD;

    for (int i = tid; i < 2048; i += 256) {
        const int r = i >> 4, cc = i & 15;
        cpasync16(qs + r * QROW + cc * 16, qg + (size_t)r * HD + cc * 8);
    }
    asm volatile("cp.async.commit_group;" ::: "memory");

    float acc[16][4];
#pragma unroll
    for (int i = 0; i < 16; i++)
#pragma unroll
        for (int q = 0; q < 4; q++) acc[i][q] = 0.f;
    float m0 = NEG_BIG, m1 = NEG_BIG, l0 = 0.f, l1 = 0.f;

    const uint32_t aB = qs + (uint32_t)(wid * 16 + (lane & 15)) * QROW + (uint32_t)(lane >> 4) * 16u;
    const uint32_t bB = ks + (uint32_t)(lane & 15) * QROW + (uint32_t)(lane >> 4) * 16u;
    const uint32_t vB = vs + (uint32_t)(lane & 15) * QROW + (uint32_t)(lane >> 4) * 16u;

    asm volatile("cp.async.wait_group 0;" ::: "memory");
    __syncthreads();

#pragma unroll 1
    for (int j = 0; j < S_LEN / 64; j++) {
        for (int i = tid; i < 1024; i += 256) {
            const int r = i >> 4, cc = i & 15;
            const size_t go = (size_t)(j * 64 + r) * HD + cc * 8;
            cpasync16(ks + r * QROW + cc * 16, kg + go);
            cpasync16(vs + r * QROW + cc * 16, vg + go);
        }
        asm volatile("cp.async.commit_group;" ::: "memory");
        asm volatile("cp.async.wait_group 0;" ::: "memory");
        __syncthreads();

        float cs[8][4];
#pragma unroll
        for (int i = 0; i < 8; i++)
#pragma unroll
            for (int q = 0; q < 4; q++) cs[i][q] = 0.f;
#pragma unroll
        for (int kd = 0; kd < 8; kd++) {
            uint32_t Aq[4];
            ldm_x4(Aq, aB + kd * 32u);
#pragma unroll
            for (int p = 0; p < 4; p++) {
                uint32_t Bq[4];
                ldm_x4(Bq, bB + (uint32_t)p * 16u * QROW + kd * 32u);
                mma16816(cs[2 * p],     Aq, Bq[0], Bq[2]);
                mma16816(cs[2 * p + 1], Aq, Bq[1], Bq[3]);
            }
        }

        float rm0 = m0, rm1 = m1;
#pragma unroll
        for (int i = 0; i < 8; i++) {
            rm0 = fmaxf(rm0, fmaxf(cs[i][0], cs[i][1]));
            rm1 = fmaxf(rm1, fmaxf(cs[i][2], cs[i][3]));
        }
        rm0 = fmaxf(rm0, __shfl_xor_sync(0xffffffffu, rm0, 1));
        rm0 = fmaxf(rm0, __shfl_xor_sync(0xffffffffu, rm0, 2));
        rm1 = fmaxf(rm1, __shfl_xor_sync(0xffffffffu, rm1, 1));
        rm1 = fmaxf(rm1, __shfl_xor_sync(0xffffffffu, rm1, 2));
        const float al0 = __expf(m0 - rm0);
        const float al1 = __expf(m1 - rm1);
        m0 = rm0; m1 = rm1;

        uint32_t ph[8][2];
        float s0 = 0.f, s1 = 0.f;
#pragma unroll
        for (int i = 0; i < 8; i++) {
            const float e0 = __expf(cs[i][0] - m0);
            const float e1 = __expf(cs[i][1] - m0);
            const float e2 = __expf(cs[i][2] - m1);
            const float e3 = __expf(cs[i][3] - m1);
            s0 += e0 + e1;  s1 += e2 + e3;
            ph[i][0] = packh2(e0, e1);
            ph[i][1] = packh2(e2, e3);
        }
        s0 += __shfl_xor_sync(0xffffffffu, s0, 1);
        s0 += __shfl_xor_sync(0xffffffffu, s0, 2);
        s1 += __shfl_xor_sync(0xffffffffu, s1, 1);
        s1 += __shfl_xor_sync(0xffffffffu, s1, 2);
        l0 = l0 * al0 + s0;
        l1 = l1 * al1 + s1;

#pragma unroll
        for (int i = 0; i < 16; i++) {
            acc[i][0] *= al0; acc[i][1] *= al0;
            acc[i][2] *= al1; acc[i][3] *= al1;
        }

#pragma unroll
        for (int kc = 0; kc < 4; kc++) {
            uint32_t Ap[4] = { ph[2 * kc][0], ph[2 * kc][1], ph[2 * kc + 1][0], ph[2 * kc + 1][1] };
#pragma unroll
            for (int dn = 0; dn < 8; dn++) {
                uint32_t Bv[4];
                ldm_x4t(Bv, vB + (uint32_t)kc * 16u * QROW + (uint32_t)dn * 32u);
                mma16816(acc[2 * dn],     Ap, Bv[0], Bv[1]);
                mma16816(acc[2 * dn + 1], Ap, Bv[2], Bv[3]);
            }
        }
        __syncthreads();
    }

    const float il0 = 1.f / l0, il1 = 1.f / l1;
    const int b = bh >> 5, h = bh & 31;
    const int tok0 = b * S_LEN + qb * 128 + wid * 16 + g;
#pragma unroll
    for (int nt = 0; nt < 16; nt++) {
        const int d0 = (nt >> 1) * 16 + (nt & 1) * 8 + 2 * t;
#pragma unroll
        for (int half8 = 0; half8 < 2; half8++) {
            const int tok = tok0 + half8 * 8;
            const float il = half8 ? il1 : il0;
            const float v0 = acc[nt][2 * half8 + 0] * il;
            const float v1 = acc[nt][2 * half8 + 1] * il;
            const __half h0 = __float2half(v0);
            const __half h1 = __float2half(v1);
            const __half q0 = __float2half(v0 - __half2float(h0));
            const __half q1 = __float2half(v1 - __half2float(h1));
            __half* base = ccat + (size_t)tok * KEFF + h * HD + d0;
            *(__half2*)base          = __halves2half2(h0, h1);
            *(__half2*)(base + HID)  = __halves2half2(q0, q1);
        }
    }
}

// ---------------------------------------------------------------------------
// Host side
// ---------------------------------------------------------------------------
extern "C" void kernel_launch(void* const* d_in, const int* in_sizes, int n_in,
                              void* d_out, int out_size)
{
    (void)in_sizes; (void)n_in; (void)out_size;
    const float* x    = (const float*)d_in[0];
    const float* qkvw = (const float*)d_in[1];
    const float* qkvb = (const float*)d_in[2];
    const float* ow   = (const float*)d_in[3];
    const float* ob   = (const float*)d_in[4];
    float* out = (float*)d_out;

    __half *qf, *kf, *vf, *xcat, *ccat, *wq, *wo;
    cudaGetSymbolAddress((void**)&qf,   g_qf);
    cudaGetSymbolAddress((void**)&kf,   g_kf);
    cudaGetSymbolAddress((void**)&vf,   g_vf);
    cudaGetSymbolAddress((void**)&xcat, g_xcat);
    cudaGetSymbolAddress((void**)&ccat, g_ccat);
    cudaGetSymbolAddress((void**)&wq,   g_wq);
    cudaGetSymbolAddress((void**)&wo,   g_wo);

    cudaFuncSetAttribute(gemm_f16s<0>, cudaFuncAttributeMaxDynamicSharedMemorySize, GEMM_DSMEM);
    cudaFuncSetAttribute(gemm_f16s<1>, cudaFuncAttributeMaxDynamicSharedMemorySize, GEMM_DSMEM);
    cudaFuncSetAttribute(flash_mma, cudaFuncAttributeMaxDynamicSharedMemorySize, FL_SMEM);

    const int napack = M_ROWS * (HID / 2);

    // 1) pack x and weights
    pack_a<<<(napack + 255) / 256, 256>>>(x, xcat, M_ROWS);
    pack_w<<<dim3(QKV_N / 32, HID / 32), dim3(32, 8)>>>(qkvw, wq, QKV_N);
    pack_w<<<dim3(HID / 32, HID / 32), dim3(32, 8)>>>(ow, wo, HID);

    // 2) q,k,v (fp16, q pre-scaled) = x @ W_qkv + b
    gemm_f16s<1><<<dim3(QKV_N / 128, M_ROWS / 128), 256, GEMM_DSMEM>>>(
        xcat, wq, qkvb, nullptr, QKV_N, qf, kf, vf);

    // 3) tensor-core flash attention -> ccat (fp16 hi|lo)
    flash_mma<<<dim3(S_LEN / 128, BATCH * NHEADS), 256, FL_SMEM>>>(qf, kf, vf, ccat);

    // 4) out = ctx @ W_o + b
    gemm_f16s<0><<<dim3(HID / 128, M_ROWS / 128), 256, GEMM_DSMEM>>>(
        ccat, wo, ob, out, HID, nullptr, nullptr, nullptr);
}

// round 11
// speedup vs baseline: 10.4330x; 1.2410x over previous
#include <cuda_runtime.h>
#include <cuda_fp16.h>
#include <math.h>
#include <stdint.h>

#define S_LEN   2048
#define BATCH   2
#define HID     4096
#define NHEADS  32
#define HD      128
#define M_ROWS  (BATCH * S_LEN)     /* 4096 */
#define QKV_N   (3 * HID)           /* 12288 */
#define KEFF    (2 * HID)           /* 8192: xcat layout stride [hi|lo] */
#define NEG_BIG (-1e30f)
#define SM_SCALE 0.088388347648318447f   /* 1/sqrt(128), folded into Q */

// ---------------------------------------------------------------------------
// Scratch (allocation-free rule: __device__ globals)
// ---------------------------------------------------------------------------
__device__ __align__(16) __half g_qf[(size_t)BATCH * NHEADS * S_LEN * HD];  // [b,h,s,d] scaled
__device__ __align__(16) __half g_kf[(size_t)BATCH * NHEADS * S_LEN * HD];
__device__ __align__(16) __half g_vf[(size_t)BATCH * NHEADS * S_LEN * HD];
__device__ __align__(16) __half g_xcat[(size_t)M_ROWS * KEFF];    // [M, 2K] = [hi|lo]
__device__ __align__(16) __half g_ctx16[(size_t)M_ROWS * HID];    // ctx plain fp16 (from flash)
__device__ __align__(16) __half g_wq[(size_t)QKV_N * HID];        // W_qkv^T [N,K] fp16
__device__ __align__(16) __half g_wo[(size_t)HID   * HID];        // W_o^T   [N,K] fp16

// ---------------------------------------------------------------------------
// helpers
// ---------------------------------------------------------------------------
__device__ __forceinline__ uint32_t su32(const void* p) {
    uint32_t a;
    asm("{ .reg .u64 t; cvta.to.shared.u64 t, %1; cvt.u32.u64 %0, t; }" : "=r"(a) : "l"(p));
    return a;
}
__device__ __forceinline__ void cpasync16(uint32_t saddr, const void* gaddr) {
    asm volatile("cp.async.cg.shared.global [%0], [%1], 16;" :: "r"(saddr), "l"(gaddr));
}
__device__ __forceinline__ void ldm_x4(uint32_t* r, uint32_t addr) {
    asm volatile("ldmatrix.sync.aligned.m8n8.x4.shared.b16 {%0,%1,%2,%3}, [%4];"
                 : "=r"(r[0]), "=r"(r[1]), "=r"(r[2]), "=r"(r[3]) : "r"(addr));
}
__device__ __forceinline__ void ldm_x4t(uint32_t* r, uint32_t addr) {
    asm volatile("ldmatrix.sync.aligned.m8n8.x4.trans.shared.b16 {%0,%1,%2,%3}, [%4];"
                 : "=r"(r[0]), "=r"(r[1]), "=r"(r[2]), "=r"(r[3]) : "r"(addr));
}
__device__ __forceinline__ void mma16816(float* c, const uint32_t* a, uint32_t b0, uint32_t b1) {
    asm volatile(
        "mma.sync.aligned.m16n8k16.row.col.f32.f16.f16.f32 "
        "{%0,%1,%2,%3}, {%4,%5,%6,%7}, {%8,%9}, {%0,%1,%2,%3};"
        : "+f"(c[0]), "+f"(c[1]), "+f"(c[2]), "+f"(c[3])
        : "r"(a[0]), "r"(a[1]), "r"(a[2]), "r"(a[3]), "r"(b0), "r"(b1));
}
__device__ __forceinline__ uint32_t packh2(float a, float b) {
    __half2 h = __floats2half2_rn(a, b);
    return *(uint32_t*)&h;
}

// ---------------------------------------------------------------------------
// Pack activations: fp32 [M, K] -> fp16 [M, 2K] as [hi | lo]
// ---------------------------------------------------------------------------
__global__ void pack_a(const float* __restrict__ in, __half* __restrict__ out, int Mr)
{
    const int idx = blockIdx.x * blockDim.x + threadIdx.x;
    if (idx >= Mr * (HID / 2)) return;
    const int row = idx / (HID / 2);
    const int k   = (idx % (HID / 2)) * 2;
    const float2 f = *(const float2*)(in + (size_t)row * HID + k);
    const __half hx = __float2half(f.x);
    const __half hy = __float2half(f.y);
    const __half lx = __float2half(f.x - __half2float(hx));
    const __half ly = __float2half(f.y - __half2float(hy));
    __half* base = out + (size_t)row * KEFF;
    *(__half2*)(base + k)       = __halves2half2(hx, hy);
    *(__half2*)(base + HID + k) = __halves2half2(lx, ly);
}

// ---------------------------------------------------------------------------
// Pack weights: fp32 [K, N] -> fp16 transposed [N, K]
// ---------------------------------------------------------------------------
__global__ void pack_w(const float* __restrict__ in, __half* __restrict__ outT, int N)
{
    __shared__ float t[32][33];
    const int nb = blockIdx.x * 32, kb = blockIdx.y * 32;
    const int tx = threadIdx.x, ty = threadIdx.y;
#pragma unroll
    for (int i = 0; i < 32; i += 8)
        t[ty + i][tx] = in[(size_t)(kb + ty + i) * N + nb + tx];
    __syncthreads();
#pragma unroll
    for (int i = 0; i < 32; i += 8) {
        const float f = t[tx][ty + i];
        outT[(size_t)(nb + ty + i) * HID + kb + tx] = __float2half(f);
    }
}

// ---------------------------------------------------------------------------
// fp16 mma.sync GEMM over real K=4096, 128x128 CTA tile, BK=32, 8 warps.
// MODE 1 (QKV): A split [hi|lo] stride KEFF; slots {Ahi, Alo, B}; 3-stage.
//               seg==2 (V) skips lo loads + lo MMAs. Epilogue -> fp16 qkv.
// MODE 0 (proj): plain fp16 A stride HID; slots {A, B}; 4-stage.
//               Epilogue -> fp32 C + bias.
// ---------------------------------------------------------------------------
#define TILE_BYTES  10240u                 /* 128 rows x 80B */
#define GEMM_DSMEM1 (3u * 3u * TILE_BYTES) /* 92160 */
#define GEMM_DSMEM0 (4u * 2u * TILE_BYTES) /* 81920 */

template<int MODE>
__global__ __launch_bounds__(256, 2)
void gemm_f16s(const __half* __restrict__ A, const __half* __restrict__ B,
               const float* __restrict__ bias, float* __restrict__ C, int Nd,
               __half* __restrict__ qf, __half* __restrict__ kf, __half* __restrict__ vf)
{
    constexpr int TILES = (MODE == 1) ? 3 : 2;
    constexpr uint32_t SLOT = (uint32_t)TILES * TILE_BYTES;
    constexpr int STG = (MODE == 1) ? 3 : 4;
    constexpr int ASTR = (MODE == 1) ? KEFF : HID;
    constexpr uint32_t BOFF = (uint32_t)(TILES - 1) * TILE_BYTES;

    extern __shared__ char smraw[];
    const uint32_t sbase = su32(smraw);

    const int tid  = threadIdx.x;
    const int lane = tid & 31, wid = tid >> 5;
    const int wm = (wid & 3) * 32, wn = (wid >> 2) * 64;
    const int m0 = blockIdx.y * 128, n0 = blockIdx.x * 128;
    const int nk = HID / 32;                       /* 128 chunks */

    const int seg = n0 >> 12;                      /* MODE1: 0=q,1=k,2=v */
    const bool use_lo = (MODE == 1) && (seg != 2);

    const __half* Ag = A + (size_t)m0 * ASTR;
    const __half* Bg = B + (size_t)n0 * HID;

    const int lrow = tid >> 2;                     /* 0..63 */
    const int lcol = (tid & 3) * 8;
    const uint32_t srowb = (uint32_t)lrow * 80u + (uint32_t)(tid & 3) * 16u;

    const uint32_t aBase = (uint32_t)(wm + (lane & 15)) * 80u + (uint32_t)(lane >> 4) * 16u;
    const uint32_t bBase = (uint32_t)(wn + (lane & 15)) * 80u + (uint32_t)(lane >> 4) * 16u;

    float c[2][8][4];
#pragma unroll
    for (int i = 0; i < 2; i++)
#pragma unroll
        for (int j = 0; j < 8; j++)
#pragma unroll
            for (int q = 0; q < 4; q++) c[i][j][q] = 0.f;

    auto issue = [&](int KT, int sl) {
        if (KT < nk) {
            const uint32_t st = sbase + (uint32_t)sl * SLOT;
            const __half* gah = Ag + (size_t)lrow * ASTR + KT * 32 + lcol;
            const __half* gb  = Bg + (size_t)lrow * HID  + KT * 32 + lcol;
            cpasync16(st + srowb,             gah);
            cpasync16(st + srowb + 64u * 80u, gah + (size_t)64 * ASTR);
            if (MODE == 1 && use_lo) {
                cpasync16(st + TILE_BYTES + srowb,             gah + HID);
                cpasync16(st + TILE_BYTES + srowb + 64u * 80u, gah + HID + (size_t)64 * KEFF);
            }
            cpasync16(st + BOFF + srowb,             gb);
            cpasync16(st + BOFF + srowb + 64u * 80u, gb + (size_t)64 * HID);
        }
        asm volatile("cp.async.commit_group;" ::: "memory");
    };

#pragma unroll
    for (int s = 0; s < STG - 1; s++) issue(s, s);

    int slot = 0;
#pragma unroll 1
    for (int kt = 0; kt < nk; kt++) {
        asm volatile("cp.async.wait_group %0;" :: "n"(STG - 2) : "memory");
        __syncthreads();
        {
            int ns = slot + STG - 1;
            if (ns >= STG) ns -= STG;
            issue(kt + STG - 1, ns);
        }

        const uint32_t sa = sbase + (uint32_t)slot * SLOT;   /* A hi */
        const uint32_t sl = sa + TILE_BYTES;                 /* A lo (MODE1) */
        const uint32_t sb = sa + BOFF;                       /* B */
#pragma unroll
        for (int kk = 0; kk < 2; kk++) {
            uint32_t A0h[4], A1h[4], A0l[4], A1l[4];
            ldm_x4(A0h, sa + aBase + kk * 32u);
            ldm_x4(A1h, sa + aBase + 1280u + kk * 32u);      /* +16 rows */
            if (MODE == 1 && use_lo) {
                ldm_x4(A0l, sl + aBase + kk * 32u);
                ldm_x4(A1l, sl + aBase + 1280u + kk * 32u);
            }
#pragma unroll
            for (int p = 0; p < 4; p++) {
                uint32_t Bq[4];
                ldm_x4(Bq, sb + bBase + (uint32_t)p * 1280u + kk * 32u);
                mma16816(c[0][2 * p],     A0h, Bq[0], Bq[2]);
                mma16816(c[0][2 * p + 1], A0h, Bq[1], Bq[3]);
                mma16816(c[1][2 * p],     A1h, Bq[0], Bq[2]);
                mma16816(c[1][2 * p + 1], A1h, Bq[1], Bq[3]);
                if (MODE == 1 && use_lo) {
                    mma16816(c[0][2 * p],     A0l, Bq[0], Bq[2]);
                    mma16816(c[0][2 * p + 1], A0l, Bq[1], Bq[3]);
                    mma16816(c[1][2 * p],     A1l, Bq[0], Bq[2]);
                    mma16816(c[1][2 * p + 1], A1l, Bq[1], Bq[3]);
                }
            }
        }
        slot = (slot + 1 >= STG) ? 0 : slot + 1;
    }

    const int gg = lane >> 2, tt = (lane & 3) * 2;

    if (MODE == 0) {
#pragma unroll
        for (int nt = 0; nt < 8; nt++) {
            const int col = n0 + wn + nt * 8 + tt;
            const float2 bb = *(const float2*)(bias + col);
#pragma unroll
            for (int mt = 0; mt < 2; mt++) {
                const int row = m0 + wm + mt * 16 + gg;
                float2 v0, v1;
                v0.x = c[mt][nt][0] + bb.x;  v0.y = c[mt][nt][1] + bb.y;
                v1.x = c[mt][nt][2] + bb.x;  v1.y = c[mt][nt][3] + bb.y;
                *(float2*)(C + (size_t)row * Nd + col)       = v0;
                *(float2*)(C + (size_t)(row + 8) * Nd + col) = v1;
            }
        }
    } else {
        const int h = (n0 >> 7) & 31;
        __half* dst = (seg == 0) ? qf : (seg == 1) ? kf : vf;
        const float sc = (seg == 0) ? SM_SCALE : 1.0f;
#pragma unroll
        for (int nt = 0; nt < 8; nt++) {
            const int col = n0 + wn + nt * 8 + tt;
            const int d   = wn + nt * 8 + tt;
            const float2 bb = *(const float2*)(bias + col);
#pragma unroll
            for (int mt = 0; mt < 2; mt++) {
                const int row = m0 + wm + mt * 16 + gg;
#pragma unroll
                for (int half8 = 0; half8 < 2; half8++) {
                    const int tok = row + half8 * 8;
                    const int b = tok >> 11, s = tok & 2047;
                    const float v0 = (c[mt][nt][2 * half8 + 0] + bb.x) * sc;
                    const float v1 = (c[mt][nt][2 * half8 + 1] + bb.y) * sc;
                    __half2* p = (__half2*)(dst + (((size_t)(b * NHEADS + h) * S_LEN + s) * HD + d));
                    *p = __floats2half2_rn(v0, v1);
                }
            }
        }
    }
}

// ---------------------------------------------------------------------------
// Tensor-core flash attention (R8 structure; epilogue now writes plain fp16):
// Br=128 (8 warps x 16 q-rows), Bc=64, fp32 acc.
// ---------------------------------------------------------------------------
#define QROW 272
#define FL_SMEM (128 * QROW + 64 * QROW + 64 * QROW)   /* 69632 */

__global__ __launch_bounds__(256, 2)
void flash_mma(const __half* __restrict__ Qf, const __half* __restrict__ Kf,
               const __half* __restrict__ Vf, __half* __restrict__ ctx16)
{
    extern __shared__ char sm8[];
    const uint32_t qs = su32(sm8);
    const uint32_t ks = qs + 128 * QROW;
    const uint32_t vs = ks + 64 * QROW;

    const int tid = threadIdx.x, lane = tid & 31, wid = tid >> 5;
    const int bh = blockIdx.y, qb = blockIdx.x;
    const int g = lane >> 2, t = lane & 3;

    const __half* qg = Qf + ((size_t)bh * S_LEN + qb * 128) * HD;
    const __half* kg = Kf + (size_t)bh * S_LEN * HD;
    const __half* vg = Vf + (size_t)bh * S_LEN * HD;

    for (int i = tid; i < 2048; i += 256) {
        const int r = i >> 4, cc = i & 15;
        cpasync16(qs + r * QROW + cc * 16, qg + (size_t)r * HD + cc * 8);
    }
    asm volatile("cp.async.commit_group;" ::: "memory");

    float acc[16][4];
#pragma unroll
    for (int i = 0; i < 16; i++)
#pragma unroll
        for (int q = 0; q < 4; q++) acc[i][q] = 0.f;
    float m0 = NEG_BIG, m1 = NEG_BIG, l0 = 0.f, l1 = 0.f;

    const uint32_t aB = qs + (uint32_t)(wid * 16 + (lane & 15)) * QROW + (uint32_t)(lane >> 4) * 16u;
    const uint32_t bB = ks + (uint32_t)(lane & 15) * QROW + (uint32_t)(lane >> 4) * 16u;
    const uint32_t vB = vs + (uint32_t)(lane & 15) * QROW + (uint32_t)(lane >> 4) * 16u;

    asm volatile("cp.async.wait_group 0;" ::: "memory");
    __syncthreads();

#pragma unroll 1
    for (int j = 0; j < S_LEN / 64; j++) {
        for (int i = tid; i < 1024; i += 256) {
            const int r = i >> 4, cc = i & 15;
            const size_t go = (size_t)(j * 64 + r) * HD + cc * 8;
            cpasync16(ks + r * QROW + cc * 16, kg + go);
            cpasync16(vs + r * QROW + cc * 16, vg + go);
        }
        asm volatile("cp.async.commit_group;" ::: "memory");
        asm volatile("cp.async.wait_group 0;" ::: "memory");
        __syncthreads();

        float cs[8][4];
#pragma unroll
        for (int i = 0; i < 8; i++)
#pragma unroll
            for (int q = 0; q < 4; q++) cs[i][q] = 0.f;
#pragma unroll
        for (int kd = 0; kd < 8; kd++) {
            uint32_t Aq[4];
            ldm_x4(Aq, aB + kd * 32u);
#pragma unroll
            for (int p = 0; p < 4; p++) {
                uint32_t Bq[4];
                ldm_x4(Bq, bB + (uint32_t)p * 16u * QROW + kd * 32u);
                mma16816(cs[2 * p],     Aq, Bq[0], Bq[2]);
                mma16816(cs[2 * p + 1], Aq, Bq[1], Bq[3]);
            }
        }

        float rm0 = m0, rm1 = m1;
#pragma unroll
        for (int i = 0; i < 8; i++) {
            rm0 = fmaxf(rm0, fmaxf(cs[i][0], cs[i][1]));
            rm1 = fmaxf(rm1, fmaxf(cs[i][2], cs[i][3]));
        }
        rm0 = fmaxf(rm0, __shfl_xor_sync(0xffffffffu, rm0, 1));
        rm0 = fmaxf(rm0, __shfl_xor_sync(0xffffffffu, rm0, 2));
        rm1 = fmaxf(rm1, __shfl_xor_sync(0xffffffffu, rm1, 1));
        rm1 = fmaxf(rm1, __shfl_xor_sync(0xffffffffu, rm1, 2));
        const float al0 = __expf(m0 - rm0);
        const float al1 = __expf(m1 - rm1);
        m0 = rm0; m1 = rm1;

        uint32_t ph[8][2];
        float s0 = 0.f, s1 = 0.f;
#pragma unroll
        for (int i = 0; i < 8; i++) {
            const float e0 = __expf(cs[i][0] - m0);
            const float e1 = __expf(cs[i][1] - m0);
            const float e2 = __expf(cs[i][2] - m1);
            const float e3 = __expf(cs[i][3] - m1);
            s0 += e0 + e1;  s1 += e2 + e3;
            ph[i][0] = packh2(e0, e1);
            ph[i][1] = packh2(e2, e3);
        }
        s0 += __shfl_xor_sync(0xffffffffu, s0, 1);
        s0 += __shfl_xor_sync(0xffffffffu, s0, 2);
        s1 += __shfl_xor_sync(0xffffffffu, s1, 1);
        s1 += __shfl_xor_sync(0xffffffffu, s1, 2);
        l0 = l0 * al0 + s0;
        l1 = l1 * al1 + s1;

#pragma unroll
        for (int i = 0; i < 16; i++) {
            acc[i][0] *= al0; acc[i][1] *= al0;
            acc[i][2] *= al1; acc[i][3] *= al1;
        }

#pragma unroll
        for (int kc = 0; kc < 4; kc++) {
            uint32_t Ap[4] = { ph[2 * kc][0], ph[2 * kc][1], ph[2 * kc + 1][0], ph[2 * kc + 1][1] };
#pragma unroll
            for (int dn = 0; dn < 8; dn++) {
                uint32_t Bv[4];
                ldm_x4t(Bv, vB + (uint32_t)kc * 16u * QROW + (uint32_t)dn * 32u);
                mma16816(acc[2 * dn],     Ap, Bv[0], Bv[1]);
                mma16816(acc[2 * dn + 1], Ap, Bv[2], Bv[3]);
            }
        }
        __syncthreads();
    }

    // Epilogue: ctx plain fp16 [tok][h*128+d]
    const float il0 = 1.f / l0, il1 = 1.f / l1;
    const int b = bh >> 5, h = bh & 31;
    const int tok0 = b * S_LEN + qb * 128 + wid * 16 + g;
#pragma unroll
    for (int nt = 0; nt < 16; nt++) {
        const int d0 = (nt >> 1) * 16 + (nt & 1) * 8 + 2 * t;
#pragma unroll
        for (int half8 = 0; half8 < 2; half8++) {
            const int tok = tok0 + half8 * 8;
            const float il = half8 ? il1 : il0;
            const float v0 = acc[nt][2 * half8 + 0] * il;
            const float v1 = acc[nt][2 * half8 + 1] * il;
            *(__half2*)(ctx16 + (size_t)tok * HID + h * HD + d0) = __floats2half2_rn(v0, v1);
        }
    }
}

// ---------------------------------------------------------------------------
// Host side
// ---------------------------------------------------------------------------
extern "C" void kernel_launch(void* const* d_in, const int* in_sizes, int n_in,
                              void* d_out, int out_size)
{
    (void)in_sizes; (void)n_in; (void)out_size;
    const float* x    = (const float*)d_in[0];
    const float* qkvw = (const float*)d_in[1];
    const float* qkvb = (const float*)d_in[2];
    const float* ow   = (const float*)d_in[3];
    const float* ob   = (const float*)d_in[4];
    float* out = (float*)d_out;

    __half *qf, *kf, *vf, *xcat, *ctx16, *wq, *wo;
    cudaGetSymbolAddress((void**)&qf,    g_qf);
    cudaGetSymbolAddress((void**)&kf,    g_kf);
    cudaGetSymbolAddress((void**)&vf,    g_vf);
    cudaGetSymbolAddress((void**)&xcat,  g_xcat);
    cudaGetSymbolAddress((void**)&ctx16, g_ctx16);
    cudaGetSymbolAddress((void**)&wq,    g_wq);
    cudaGetSymbolAddress((void**)&wo,    g_wo);

    cudaFuncSetAttribute(gemm_f16s<1>, cudaFuncAttributeMaxDynamicSharedMemorySize, GEMM_DSMEM1);
    cudaFuncSetAttribute(gemm_f16s<0>, cudaFuncAttributeMaxDynamicSharedMemorySize, GEMM_DSMEM0);
    cudaFuncSetAttribute(flash_mma, cudaFuncAttributeMaxDynamicSharedMemorySize, FL_SMEM);

    const int napack = M_ROWS * (HID / 2);

    // 1) pack x and weights
    pack_a<<<(napack + 255) / 256, 256>>>(x, xcat, M_ROWS);
    pack_w<<<dim3(QKV_N / 32, HID / 32), dim3(32, 8)>>>(qkvw, wq, QKV_N);
    pack_w<<<dim3(HID / 32, HID / 32), dim3(32, 8)>>>(ow, wo, HID);

    // 2) q,k,v (fp16, q pre-scaled) = x @ W_qkv + b  (split A; V columns hi-only)
    gemm_f16s<1><<<dim3(QKV_N / 128, M_ROWS / 128), 256, GEMM_DSMEM1>>>(
        xcat, wq, qkvb, nullptr, QKV_N, qf, kf, vf);

    // 3) tensor-core flash attention -> ctx16 (plain fp16)
    flash_mma<<<dim3(S_LEN / 128, BATCH * NHEADS), 256, FL_SMEM>>>(qf, kf, vf, ctx16);

    // 4) out = ctx @ W_o + b  (plain fp16 GEMM)
    gemm_f16s<0><<<dim3(HID / 128, M_ROWS / 128), 256, GEMM_DSMEM0>>>(
        ctx16, wo, ob, out, HID, nullptr, nullptr, nullptr);
}

// round 12
// speedup vs baseline: 14.4447x; 1.3845x over previous
#include <cuda_runtime.h>
#include <cuda_fp16.h>
#include <math.h>
#include <stdint.h>

#define S_LEN   2048
#define BATCH   2
#define HID     4096
#define NHEADS  32
#define HD      128
#define M_ROWS  (BATCH * S_LEN)     /* 4096 */
#define QKV_N   (3 * HID)           /* 12288 */
#define NEG_BIG (-1e30f)
#define SM_SCALE 0.088388347648318447f   /* 1/sqrt(128), folded into Q */

// ---------------------------------------------------------------------------
// Scratch (allocation-free rule: __device__ globals)
// ---------------------------------------------------------------------------
__device__ __align__(16) __half g_qf[(size_t)BATCH * NHEADS * S_LEN * HD];  // [b,h,s,d] scaled
__device__ __align__(16) __half g_kf[(size_t)BATCH * NHEADS * S_LEN * HD];
__device__ __align__(16) __half g_vf[(size_t)BATCH * NHEADS * S_LEN * HD];
__device__ __align__(16) __half g_x16[(size_t)M_ROWS * HID];      // x fp16
__device__ __align__(16) __half g_ctx16[(size_t)M_ROWS * HID];    // ctx fp16 (from flash)
__device__ __align__(16) __half g_wq[(size_t)QKV_N * HID];        // W_qkv^T [N,K] fp16
__device__ __align__(16) __half g_wo[(size_t)HID   * HID];        // W_o^T   [N,K] fp16

// ---------------------------------------------------------------------------
// helpers
// ---------------------------------------------------------------------------
__device__ __forceinline__ uint32_t su32(const void* p) {
    uint32_t a;
    asm("{ .reg .u64 t; cvta.to.shared.u64 t, %1; cvt.u32.u64 %0, t; }" : "=r"(a) : "l"(p));
    return a;
}
__device__ __forceinline__ void cpasync16(uint32_t saddr, const void* gaddr) {
    asm volatile("cp.async.cg.shared.global [%0], [%1], 16;" :: "r"(saddr), "l"(gaddr));
}
__device__ __forceinline__ void ldm_x4(uint32_t* r, uint32_t addr) {
    asm volatile("ldmatrix.sync.aligned.m8n8.x4.shared.b16 {%0,%1,%2,%3}, [%4];"
                 : "=r"(r[0]), "=r"(r[1]), "=r"(r[2]), "=r"(r[3]) : "r"(addr));
}
__device__ __forceinline__ void ldm_x4t(uint32_t* r, uint32_t addr) {
    asm volatile("ldmatrix.sync.aligned.m8n8.x4.trans.shared.b16 {%0,%1,%2,%3}, [%4];"
                 : "=r"(r[0]), "=r"(r[1]), "=r"(r[2]), "=r"(r[3]) : "r"(addr));
}
__device__ __forceinline__ void mma16816(float* c, const uint32_t* a, uint32_t b0, uint32_t b1) {
    asm volatile(
        "mma.sync.aligned.m16n8k16.row.col.f32.f16.f16.f32 "
        "{%0,%1,%2,%3}, {%4,%5,%6,%7}, {%8,%9}, {%0,%1,%2,%3};"
        : "+f"(c[0]), "+f"(c[1]), "+f"(c[2]), "+f"(c[3])
        : "r"(a[0]), "r"(a[1]), "r"(a[2]), "r"(a[3]), "r"(b0), "r"(b1));
}
__device__ __forceinline__ uint32_t packh2(float a, float b) {
    __half2 h = __floats2half2_rn(a, b);
    return *(uint32_t*)&h;
}

// ---------------------------------------------------------------------------
// Pack activations: fp32 -> fp16 (plain convert)
// ---------------------------------------------------------------------------
__global__ void pack_a(const float* __restrict__ in, __half* __restrict__ out, int n4)
{
    const int i = blockIdx.x * blockDim.x + threadIdx.x;
    if (i >= n4) return;
    const float4 f = ((const float4*)in)[i];
    __half2* p = (__half2*)out + (size_t)i * 2;
    p[0] = __floats2half2_rn(f.x, f.y);
    p[1] = __floats2half2_rn(f.z, f.w);
}

// ---------------------------------------------------------------------------
// Pack weights: fp32 [K, N] -> fp16 transposed [N, K]
// ---------------------------------------------------------------------------
__global__ void pack_w(const float* __restrict__ in, __half* __restrict__ outT, int N)
{
    __shared__ float t[32][33];
    const int nb = blockIdx.x * 32, kb = blockIdx.y * 32;
    const int tx = threadIdx.x, ty = threadIdx.y;
#pragma unroll
    for (int i = 0; i < 32; i += 8)
        t[ty + i][tx] = in[(size_t)(kb + ty + i) * N + nb + tx];
    __syncthreads();
#pragma unroll
    for (int i = 0; i < 32; i += 8) {
        const float f = t[tx][ty + i];
        outT[(size_t)(nb + ty + i) * HID + kb + tx] = __float2half(f);
    }
}

// ---------------------------------------------------------------------------
// Plain fp16 mma.sync GEMM over K=4096, 128x128 CTA tile, BK=32, 8 warps,
// 4-stage cp.async, warp 32x64. Template MODE selects epilogue only:
// MODE 0 (proj): fp32 C + bias.  MODE 1 (QKV): fp16 q/k/v [b,h,s,d], Q scaled.
// ---------------------------------------------------------------------------
#define TILE_BYTES  10240u                 /* 128 rows x 80B */
#define GSTG        4
#define SLOT_BYTES  (2u * TILE_BYTES)      /* A + B */
#define GEMM_DSMEM  (GSTG * SLOT_BYTES)    /* 81920 */

template<int MODE>
__global__ __launch_bounds__(256, 2)
void gemm_f16s(const __half* __restrict__ A, const __half* __restrict__ B,
               const float* __restrict__ bias, float* __restrict__ C, int Nd,
               __half* __restrict__ qf, __half* __restrict__ kf, __half* __restrict__ vf)
{
    extern __shared__ char smraw[];
    const uint32_t sbase = su32(smraw);

    const int tid  = threadIdx.x;
    const int lane = tid & 31, wid = tid >> 5;
    const int wm = (wid & 3) * 32, wn = (wid >> 2) * 64;
    const int m0 = blockIdx.y * 128, n0 = blockIdx.x * 128;
    const int nk = HID / 32;                       /* 128 chunks */

    const __half* Ag = A + (size_t)m0 * HID;
    const __half* Bg = B + (size_t)n0 * HID;

    const int lrow = tid >> 2;                     /* 0..63 */
    const int lcol = (tid & 3) * 8;
    const uint32_t srowb = (uint32_t)lrow * 80u + (uint32_t)(tid & 3) * 16u;

    const uint32_t aBase = (uint32_t)(wm + (lane & 15)) * 80u + (uint32_t)(lane >> 4) * 16u;
    const uint32_t bBase = (uint32_t)(wn + (lane & 15)) * 80u + (uint32_t)(lane >> 4) * 16u;

    float c[2][8][4];
#pragma unroll
    for (int i = 0; i < 2; i++)
#pragma unroll
        for (int j = 0; j < 8; j++)
#pragma unroll
            for (int q = 0; q < 4; q++) c[i][j][q] = 0.f;

    auto issue = [&](int KT, int sl) {
        if (KT < nk) {
            const uint32_t st = sbase + (uint32_t)sl * SLOT_BYTES;
            const __half* ga = Ag + (size_t)lrow * HID + KT * 32 + lcol;
            const __half* gb = Bg + (size_t)lrow * HID + KT * 32 + lcol;
            cpasync16(st + srowb,                          ga);
            cpasync16(st + srowb + 64u * 80u,              ga + (size_t)64 * HID);
            cpasync16(st + TILE_BYTES + srowb,             gb);
            cpasync16(st + TILE_BYTES + srowb + 64u * 80u, gb + (size_t)64 * HID);
        }
        asm volatile("cp.async.commit_group;" ::: "memory");
    };

#pragma unroll
    for (int s = 0; s < GSTG - 1; s++) issue(s, s);

    int slot = 0;
#pragma unroll 1
    for (int kt = 0; kt < nk; kt++) {
        asm volatile("cp.async.wait_group %0;" :: "n"(GSTG - 2) : "memory");
        __syncthreads();
        {
            int ns = slot + GSTG - 1;
            if (ns >= GSTG) ns -= GSTG;
            issue(kt + GSTG - 1, ns);
        }

        const uint32_t sa = sbase + (uint32_t)slot * SLOT_BYTES;
        const uint32_t sb = sa + TILE_BYTES;
#pragma unroll
        for (int kk = 0; kk < 2; kk++) {
            uint32_t A0[4], A1[4];
            ldm_x4(A0, sa + aBase + kk * 32u);
            ldm_x4(A1, sa + aBase + 1280u + kk * 32u);      /* +16 rows */
#pragma unroll
            for (int p = 0; p < 4; p++) {
                uint32_t Bq[4];
                ldm_x4(Bq, sb + bBase + (uint32_t)p * 1280u + kk * 32u);
                mma16816(c[0][2 * p],     A0, Bq[0], Bq[2]);
                mma16816(c[0][2 * p + 1], A0, Bq[1], Bq[3]);
                mma16816(c[1][2 * p],     A1, Bq[0], Bq[2]);
                mma16816(c[1][2 * p + 1], A1, Bq[1], Bq[3]);
            }
        }
        slot = (slot + 1 >= GSTG) ? 0 : slot + 1;
    }

    const int gg = lane >> 2, tt = (lane & 3) * 2;

    if (MODE == 0) {
#pragma unroll
        for (int nt = 0; nt < 8; nt++) {
            const int col = n0 + wn + nt * 8 + tt;
            const float2 bb = *(const float2*)(bias + col);
#pragma unroll
            for (int mt = 0; mt < 2; mt++) {
                const int row = m0 + wm + mt * 16 + gg;
                float2 v0, v1;
                v0.x = c[mt][nt][0] + bb.x;  v0.y = c[mt][nt][1] + bb.y;
                v1.x = c[mt][nt][2] + bb.x;  v1.y = c[mt][nt][3] + bb.y;
                *(float2*)(C + (size_t)row * Nd + col)       = v0;
                *(float2*)(C + (size_t)(row + 8) * Nd + col) = v1;
            }
        }
    } else {
        const int seg = n0 >> 12;               /* 0=q, 1=k, 2=v */
        const int h   = (n0 >> 7) & 31;
        __half* dst = (seg == 0) ? qf : (seg == 1) ? kf : vf;
        const float sc = (seg == 0) ? SM_SCALE : 1.0f;
#pragma unroll
        for (int nt = 0; nt < 8; nt++) {
            const int col = n0 + wn + nt * 8 + tt;
            const int d   = wn + nt * 8 + tt;
            const float2 bb = *(const float2*)(bias + col);
#pragma unroll
            for (int mt = 0; mt < 2; mt++) {
                const int row = m0 + wm + mt * 16 + gg;
#pragma unroll
                for (int half8 = 0; half8 < 2; half8++) {
                    const int tok = row + half8 * 8;
                    const int b = tok >> 11, s = tok & 2047;
                    const float v0 = (c[mt][nt][2 * half8 + 0] + bb.x) * sc;
                    const float v1 = (c[mt][nt][2 * half8 + 1] + bb.y) * sc;
                    __half2* p = (__half2*)(dst + (((size_t)(b * NHEADS + h) * S_LEN + s) * HD + d));
                    *p = __floats2half2_rn(v0, v1);
                }
            }
        }
    }
}

// ---------------------------------------------------------------------------
// Tensor-core flash attention: Br=128 (8 warps x 16 q-rows), Bc=64, fp32 acc.
// ---------------------------------------------------------------------------
#define QROW 272
#define FL_SMEM (128 * QROW + 64 * QROW + 64 * QROW)   /* 69632 */

__global__ __launch_bounds__(256, 2)
void flash_mma(const __half* __restrict__ Qf, const __half* __restrict__ Kf,
               const __half* __restrict__ Vf, __half* __restrict__ ctx16)
{
    extern __shared__ char sm8[];
    const uint32_t qs = su32(sm8);
    const uint32_t ks = qs + 128 * QROW;
    const uint32_t vs = ks + 64 * QROW;

    const int tid = threadIdx.x, lane = tid & 31, wid = tid >> 5;
    const int bh = blockIdx.y, qb = blockIdx.x;
    const int g = lane >> 2, t = lane & 3;

    const __half* qg = Qf + ((size_t)bh * S_LEN + qb * 128) * HD;
    const __half* kg = Kf + (size_t)bh * S_LEN * HD;
    const __half* vg = Vf + (size_t)bh * S_LEN * HD;

    for (int i = tid; i < 2048; i += 256) {
        const int r = i >> 4, cc = i & 15;
        cpasync16(qs + r * QROW + cc * 16, qg + (size_t)r * HD + cc * 8);
    }
    asm volatile("cp.async.commit_group;" ::: "memory");

    float acc[16][4];
#pragma unroll
    for (int i = 0; i < 16; i++)
#pragma unroll
        for (int q = 0; q < 4; q++) acc[i][q] = 0.f;
    float m0 = NEG_BIG, m1 = NEG_BIG, l0 = 0.f, l1 = 0.f;

    const uint32_t aB = qs + (uint32_t)(wid * 16 + (lane & 15)) * QROW + (uint32_t)(lane >> 4) * 16u;
    const uint32_t bB = ks + (uint32_t)(lane & 15) * QROW + (uint32_t)(lane >> 4) * 16u;
    const uint32_t vB = vs + (uint32_t)(lane & 15) * QROW + (uint32_t)(lane >> 4) * 16u;

    asm volatile("cp.async.wait_group 0;" ::: "memory");
    __syncthreads();

#pragma unroll 1
    for (int j = 0; j < S_LEN / 64; j++) {
        for (int i = tid; i < 1024; i += 256) {
            const int r = i >> 4, cc = i & 15;
            const size_t go = (size_t)(j * 64 + r) * HD + cc * 8;
            cpasync16(ks + r * QROW + cc * 16, kg + go);
            cpasync16(vs + r * QROW + cc * 16, vg + go);
        }
        asm volatile("cp.async.commit_group;" ::: "memory");
        asm volatile("cp.async.wait_group 0;" ::: "memory");
        __syncthreads();

        float cs[8][4];
#pragma unroll
        for (int i = 0; i < 8; i++)
#pragma unroll
            for (int q = 0; q < 4; q++) cs[i][q] = 0.f;
#pragma unroll
        for (int kd = 0; kd < 8; kd++) {
            uint32_t Aq[4];
            ldm_x4(Aq, aB + kd * 32u);
#pragma unroll
            for (int p = 0; p < 4; p++) {
                uint32_t Bq[4];
                ldm_x4(Bq, bB + (uint32_t)p * 16u * QROW + kd * 32u);
                mma16816(cs[2 * p],     Aq, Bq[0], Bq[2]);
                mma16816(cs[2 * p + 1], Aq, Bq[1], Bq[3]);
            }
        }

        float rm0 = m0, rm1 = m1;
#pragma unroll
        for (int i = 0; i < 8; i++) {
            rm0 = fmaxf(rm0, fmaxf(cs[i][0], cs[i][1]));
            rm1 = fmaxf(rm1, fmaxf(cs[i][2], cs[i][3]));
        }
        rm0 = fmaxf(rm0, __shfl_xor_sync(0xffffffffu, rm0, 1));
        rm0 = fmaxf(rm0, __shfl_xor_sync(0xffffffffu, rm0, 2));
        rm1 = fmaxf(rm1, __shfl_xor_sync(0xffffffffu, rm1, 1));
        rm1 = fmaxf(rm1, __shfl_xor_sync(0xffffffffu, rm1, 2));
        const float al0 = __expf(m0 - rm0);
        const float al1 = __expf(m1 - rm1);
        m0 = rm0; m1 = rm1;

        uint32_t ph[8][2];
        float s0 = 0.f, s1 = 0.f;
#pragma unroll
        for (int i = 0; i < 8; i++) {
            const float e0 = __expf(cs[i][0] - m0);
            const float e1 = __expf(cs[i][1] - m0);
            const float e2 = __expf(cs[i][2] - m1);
            const float e3 = __expf(cs[i][3] - m1);
            s0 += e0 + e1;  s1 += e2 + e3;
            ph[i][0] = packh2(e0, e1);
            ph[i][1] = packh2(e2, e3);
        }
        s0 += __shfl_xor_sync(0xffffffffu, s0, 1);
        s0 += __shfl_xor_sync(0xffffffffu, s0, 2);
        s1 += __shfl_xor_sync(0xffffffffu, s1, 1);
        s1 += __shfl_xor_sync(0xffffffffu, s1, 2);
        l0 = l0 * al0 + s0;
        l1 = l1 * al1 + s1;

#pragma unroll
        for (int i = 0; i < 16; i++) {
            acc[i][0] *= al0; acc[i][1] *= al0;
            acc[i][2] *= al1; acc[i][3] *= al1;
        }

#pragma unroll
        for (int kc = 0; kc < 4; kc++) {
            uint32_t Ap[4] = { ph[2 * kc][0], ph[2 * kc][1], ph[2 * kc + 1][0], ph[2 * kc + 1][1] };
#pragma unroll
            for (int dn = 0; dn < 8; dn++) {
                uint32_t Bv[4];
                ldm_x4t(Bv, vB + (uint32_t)kc * 16u * QROW + (uint32_t)dn * 32u);
                mma16816(acc[2 * dn],     Ap, Bv[0], Bv[1]);
                mma16816(acc[2 * dn + 1], Ap, Bv[2], Bv[3]);
            }
        }
        __syncthreads();
    }

    // Epilogue: ctx plain fp16 [tok][h*128+d]
    const float il0 = 1.f / l0, il1 = 1.f / l1;
    const int b = bh >> 5, h = bh & 31;
    const int tok0 = b * S_LEN + qb * 128 + wid * 16 + g;
#pragma unroll
    for (int nt = 0; nt < 16; nt++) {
        const int d0 = (nt >> 1) * 16 + (nt & 1) * 8 + 2 * t;
#pragma unroll
        for (int half8 = 0; half8 < 2; half8++) {
            const int tok = tok0 + half8 * 8;
            const float il = half8 ? il1 : il0;
            const float v0 = acc[nt][2 * half8 + 0] * il;
            const float v1 = acc[nt][2 * half8 + 1] * il;
            *(__half2*)(ctx16 + (size_t)tok * HID + h * HD + d0) = __floats2half2_rn(v0, v1);
        }
    }
}

// ---------------------------------------------------------------------------
// Host side
// ---------------------------------------------------------------------------
extern "C" void kernel_launch(void* const* d_in, const int* in_sizes, int n_in,
                              void* d_out, int out_size)
{
    (void)in_sizes; (void)n_in; (void)out_size;
    const float* x    = (const float*)d_in[0];
    const float* qkvw = (const float*)d_in[1];
    const float* qkvb = (const float*)d_in[2];
    const float* ow   = (const float*)d_in[3];
    const float* ob   = (const float*)d_in[4];
    float* out = (float*)d_out;

    __half *qf, *kf, *vf, *x16, *ctx16, *wq, *wo;
    cudaGetSymbolAddress((void**)&qf,    g_qf);
    cudaGetSymbolAddress((void**)&kf,    g_kf);
    cudaGetSymbolAddress((void**)&vf,    g_vf);
    cudaGetSymbolAddress((void**)&x16,   g_x16);
    cudaGetSymbolAddress((void**)&ctx16, g_ctx16);
    cudaGetSymbolAddress((void**)&wq,    g_wq);
    cudaGetSymbolAddress((void**)&wo,    g_wo);

    cudaFuncSetAttribute(gemm_f16s<1>, cudaFuncAttributeMaxDynamicSharedMemorySize, GEMM_DSMEM);
    cudaFuncSetAttribute(gemm_f16s<0>, cudaFuncAttributeMaxDynamicSharedMemorySize, GEMM_DSMEM);
    cudaFuncSetAttribute(flash_mma, cudaFuncAttributeMaxDynamicSharedMemorySize, FL_SMEM);

    const int n4 = M_ROWS * HID / 4;

    // 1) pack x and weights to fp16
    pack_a<<<(n4 + 255) / 256, 256>>>(x, x16, n4);
    pack_w<<<dim3(QKV_N / 32, HID / 32), dim3(32, 8)>>>(qkvw, wq, QKV_N);
    pack_w<<<dim3(HID / 32, HID / 32), dim3(32, 8)>>>(ow, wo, HID);

    // 2) q,k,v (fp16, q pre-scaled) = x @ W_qkv + b  (plain fp16)
    gemm_f16s<1><<<dim3(QKV_N / 128, M_ROWS / 128), 256, GEMM_DSMEM>>>(
        x16, wq, qkvb, nullptr, QKV_N, qf, kf, vf);

    // 3) tensor-core flash attention -> ctx16 (fp16)
    flash_mma<<<dim3(S_LEN / 128, BATCH * NHEADS), 256, FL_SMEM>>>(qf, kf, vf, ctx16);

    // 4) out = ctx @ W_o + b  (plain fp16)
    gemm_f16s<0><<<dim3(HID / 128, M_ROWS / 128), 256, GEMM_DSMEM>>>(
        ctx16, wo, ob, out, HID, nullptr, nullptr, nullptr);
}